// round 12
// baseline (speedup 1.0000x reference)
#include <cuda_runtime.h>
#include <cstdint>
#include <math.h>

// Problem dims
#define LSEQ   1024
#define G3     768        // 3*OUT_H
#define HID    256        // OUT_H
#define NTAGS  6
#define CLN    16         // cluster size per cell
#define START_TAG 4
#define CHUNK  64
#define CSHIFT 6
#define NCHUNK (LSEQ / CHUNK)
#define NWORK1 24         // Gi1 GEMM worker CTAs
#define NWORK0 24         // Gi0 GEMM worker CTAs
#define NEO    4          // log_softmax worker CTAs
#define NRECUR 64         // 4 cells x 16 CTAs
#define GRID_TOTAL 128    // 64 + 24 + 24 + 4 = 116, padded to multiple of CLN

// ---------------- scratch (device globals; no allocation) ----------------
__device__ __align__(16) float g_GiF [LSEQ * G3];
__device__ __align__(16) float g_GiB [LSEQ * G3];
__device__ __align__(16) float g_Gi1F[LSEQ * G3];
__device__ __align__(16) float g_Gi1B[LSEQ * G3];
__device__ __align__(16) float g_O0 [LSEQ * 512];
__device__ __align__(16) float g_H1 [LSEQ * 512];
__device__ __align__(16) float g_EO [LSEQ * 512];
__device__ int   g_G0flag[NCHUNK];   // counts to NWORK0 (Gi0 tiles ready)
__device__ int   g_L0flag[NCHUNK];   // counts to 32 (L0 CTAs done with chunk)
__device__ int   g_Gflag [NCHUNK];   // counts to NWORK1 (Gi1 tiles ready)
__device__ int   g_H1flag[NCHUNK];   // counts to 32 (L1 CTAs done with chunk)
// decoder staging
__device__ __align__(16) float g_awl [NTAGS * 1024];
__device__ __align__(16) float g_ctxp[16 * NTAGS * 512];
__device__ __align__(16) float g_cat2[NTAGS * 1024];
__device__ __align__(16) float g_oo  [NTAGS * 512];
__device__ __align__(16) float g_gi  [NTAGS * 1536];
__device__ __align__(16) float g_gh  [1536];

// ---------------- helpers ----------------
__device__ __forceinline__ float wred_sum(float v) {
#pragma unroll
    for (int o = 16; o; o >>= 1) v += __shfl_xor_sync(0xffffffffu, v, o);
    return v;
}
__device__ __forceinline__ float wred_max(float v) {
#pragma unroll
    for (int o = 16; o; o >>= 1) v = fmaxf(v, __shfl_xor_sync(0xffffffffu, v, o));
    return v;
}
__device__ __forceinline__ float sigm(float x) { return 1.0f / (1.0f + expf(-x)); }
__device__ __forceinline__ float fsigm(float x) { return __fdividef(1.0f, 1.0f + __expf(-x)); }
__device__ __forceinline__ float ftanh(float x) {
    return 1.0f - __fdividef(2.0f, __expf(2.0f * x) + 1.0f);
}
__device__ __forceinline__ void cluster_sync_asm() {
    asm volatile("barrier.cluster.arrive.aligned;" ::: "memory");
    asm volatile("barrier.cluster.wait.aligned;" ::: "memory");
}
__device__ __forceinline__ uint32_t mapa_sc(uint32_t la, uint32_t r) {
    uint32_t ra;
    asm("mapa.shared::cluster.u32 %0, %1, %2;" : "=r"(ra) : "r"(la), "r"(r));
    return ra;
}
// DSMEM bulk copy: one 64B message per (src CTA -> dst CTA), complete_tx on dest barrier
__device__ __forceinline__ void bulk_c2c(uint32_t dst, uint32_t src, uint32_t bytes, uint32_t rmbar) {
    asm volatile("cp.async.bulk.shared::cluster.shared::cta.mbarrier::complete_tx::bytes [%0], [%1], %2, [%3];"
                 :: "r"(dst), "r"(src), "r"(bytes), "r"(rmbar) : "memory");
}
__device__ __forceinline__ void fence_proxy_async_cta() {
    asm volatile("fence.proxy.async.shared::cta;" ::: "memory");
}
__device__ __forceinline__ void mbar_init(uint32_t mb, uint32_t cnt) {
    asm volatile("mbarrier.init.shared.b64 [%0], %1;" :: "r"(mb), "r"(cnt) : "memory");
}
__device__ __forceinline__ void mbar_arrive_expect(uint32_t mb, uint32_t bytes) {
    asm volatile("mbarrier.arrive.expect_tx.shared.b64 _, [%0], %1;" :: "r"(mb), "r"(bytes) : "memory");
}
__device__ __forceinline__ void mbar_wait_parity(uint32_t mb, uint32_t parity) {
    uint32_t done;
    asm volatile(
        "{\n\t.reg .pred p;\n\t"
        "mbarrier.try_wait.parity.acquire.cluster.shared::cta.b64 p, [%1], %2;\n\t"
        "selp.b32 %0, 1, 0, p;\n\t}"
        : "=r"(done) : "r"(mb), "r"(parity) : "memory");
    if (!done) {
        asm volatile(
            "{\n\t.reg .pred P1;\n\t"
            "WL_%=:\n\t"
            "mbarrier.try_wait.parity.acquire.cluster.shared::cta.b64 P1, [%0], %1, 0x989680;\n\t"
            "@P1 bra.uni WD_%=;\n\t"
            "bra.uni WL_%=;\n\t"
            "WD_%=:\n\t}"
            :: "r"(mb), "r"(parity) : "memory");
    }
}
__device__ __forceinline__ int ld_acq_gpu(const int* p) {
    int v;
    asm volatile("ld.acquire.gpu.global.b32 %0, [%1];" : "=r"(v) : "l"(p) : "memory");
    return v;
}
__device__ __forceinline__ void membar_gpu() {
    asm volatile("membar.gl;" ::: "memory");
}

// ---------------- flag init ----------------
__global__ void init_flags_kernel()
{
    int i = threadIdx.x;
    if (i < NCHUNK) {
        g_G0flag[i] = 0;
        g_L0flag[i] = 0;
        g_Gflag[i]  = 0;
        g_H1flag[i] = 0;
    }
}

// ---------------- fused pipelined encoder ----------------
// bid 0-63:    4 clusters of 16 = cells L0f, L0b, L1f, L1b (recurrence)
// bid 64-87:   24 Gi1 workers (wait L0flag)
// bid 88-111:  24 Gi0 workers (no wait)
// bid 112-115: 4 EO workers (wait H1flag)
// bid 116-127: pad, exit
__global__ void __cluster_dims__(CLN, 1, 1) fused_kernel(
    const float* __restrict__ Whh0f, const float* __restrict__ bhh0f,
    const float* __restrict__ Whh0b, const float* __restrict__ bhh0b,
    const float* __restrict__ Whh1f, const float* __restrict__ bhh1f,
    const float* __restrict__ Whh1b, const float* __restrict__ bhh1b,
    const float* __restrict__ Wih1f, const float* __restrict__ bih1f,
    const float* __restrict__ Wih1b, const float* __restrict__ bih1b,
    const float* __restrict__ Wih0f, const float* __restrict__ bih0f,
    const float* __restrict__ Wih0b, const float* __restrict__ bih0b,
    const int*   __restrict__ x,     const float* __restrict__ emb,
    const float* __restrict__ hinit)
{
    __shared__ __align__(16) float hbuf[2][256];
    __shared__ __align__(16) float stg[2][12 * 16];   // per-warp 64B staging, double-buffered
    __shared__ __align__(16) float red3[48];
    __shared__ __align__(16) float gis[48];
    __shared__ __align__(16) float bhhs[48];
    __shared__ __align__(16) float As[32][68];
    __shared__ __align__(16) float Bs[32][68];
    __shared__ __align__(8)  uint64_t s_mb;

    int bid = blockIdx.x;
    int tid = threadIdx.x;

    if (bid < NRECUR) {
        // ================= recurrence cell =================
        int cell = bid >> 4;          // 0=L0f 1=L0b 2=L1f 3=L1b
        int isL1 = cell >> 1;
        int col  = cell & 1;
        unsigned rank;
        asm("mov.u32 %0, %%cluster_ctarank;" : "=r"(rank));

        const float* Gi  = isL1 ? (col ? g_Gi1B : g_Gi1F) : (col ? g_GiB : g_GiF);
        const float* Whh = (cell == 0) ? Whh0f : (cell == 1) ? Whh0b : (cell == 2) ? Whh1f : Whh1b;
        const float* bhh = (cell == 0) ? bhh0f : (cell == 1) ? bhh0b : (cell == 2) ? bhh1f : bhh1b;
        float* Out       = isL1 ? g_H1 : g_O0;
        const int* inFlag = isL1 ? g_Gflag : g_G0flag;
        int inTarget      = isL1 ? NWORK1 : NWORK0;
        int* outFlag      = isL1 ? g_H1flag : g_L0flag;

        int q  = tid & 7;             // K-chunk of 32
        int rl = tid >> 3;            // 0..47  (gate-row local)
        int g  = rl >> 4, jj = rl & 15;
        int rowGlobal = g * 256 + (int)rank * 16 + jj;
        int w    = tid >> 5;
        int lane = tid & 31;

        // weights loaded in q-rotated order so the h-read is bank-conflict-free
        float4 w4[8];
        const float* wp = Whh + (size_t)rowGlobal * 256 + q * 32;
#pragma unroll
        for (int i = 0; i < 8; i++) {
            int ii = (i + q) & 7;
            w4[i] = *(const float4*)(wp + ii * 4);
        }

        uint32_t mb = (uint32_t)__cvta_generic_to_shared(&s_mb);
        if (tid == 0) mbar_init(mb, 1);
        if (tid < 256) hbuf[0][tid] = hinit[cell * 256 + tid];
        if (tid < 48)  bhhs[tid] = bhh[(tid >> 4) * 256 + (int)rank * 16 + (tid & 15)];
        __syncthreads();
        cluster_sync_asm();   // one-time: peers' mbarriers + hbuf[0] ready

        // bulk-copy addresses: warp w -> dest CTA w; warps 8-11 also -> dest w+4.
        // dst = dest CTA's hbuf[buf] segment for OUR rank; src = our warp's staging slot.
        uint32_t dstA0, dstA1, rma, srcS0, srcS1;
        uint32_t dstB0 = 0, dstB1 = 0, rmb2 = 0;
        {
            uint32_t la0 = (uint32_t)__cvta_generic_to_shared(&hbuf[0][rank * 16]);
            uint32_t la1 = (uint32_t)__cvta_generic_to_shared(&hbuf[1][rank * 16]);
            dstA0 = mapa_sc(la0, (uint32_t)w);
            dstA1 = mapa_sc(la1, (uint32_t)w);
            rma   = mapa_sc(mb,  (uint32_t)w);
            if (w >= 8) {
                dstB0 = mapa_sc(la0, (uint32_t)(w + 4));
                dstB1 = mapa_sc(la1, (uint32_t)(w + 4));
                rmb2  = mapa_sc(mb,  (uint32_t)(w + 4));
            }
            srcS0 = (uint32_t)__cvta_generic_to_shared(&stg[0][w * 16]);
            srcS1 = (uint32_t)__cvta_generic_to_shared(&stg[1][w * 16]);
        }

        float gi_cur = 0.f;

        for (int t = 0; t < LSEQ; t++) {
            int cur = t & 1;
            bool last = (t == LSEQ - 1);

            if ((t & (CHUNK - 1)) == 0) {
                if (tid == 0) {
                    int k = t >> CSHIFT;
                    while (ld_acq_gpu(&inFlag[k]) < inTarget) __nanosleep(128);
                }
                __syncthreads();
                if (tid < 48) gi_cur = Gi[(size_t)t * G3 + (tid >> 4) * 256 + (int)rank * 16 + (tid & 15)];
            }

            if (!last && tid == 0) mbar_arrive_expect(mb, 1024);
            if (tid < 48) {
                gis[tid] = gi_cur;
                bool pf = (t + 1 < LSEQ) && (((t + 1) & (CHUNK - 1)) != 0);
                if (pf) gi_cur = Gi[(size_t)(t + 1) * G3 + (tid >> 4) * 256 + (int)rank * 16 + (tid & 15)];
            }

            // partial dot: thread covers k in [q*32, q*32+32), q-rotated access order
            const float* hc = hbuf[cur] + q * 32;
            float ax = 0.f, ay = 0.f, az = 0.f, aw = 0.f;
#pragma unroll
            for (int i = 0; i < 8; i++) {
                int ii = (i + q) & 7;
                float4 hv = *(const float4*)(hc + ii * 4);
                ax += w4[i].x * hv.x; ay += w4[i].y * hv.y;
                az += w4[i].z * hv.z; aw += w4[i].w * hv.w;
            }
            float v = (ax + ay) + (az + aw);
            v += __shfl_xor_sync(0xffffffffu, v, 1);
            v += __shfl_xor_sync(0xffffffffu, v, 2);
            v += __shfl_xor_sync(0xffffffffu, v, 4);
            if (q == 0) red3[rl] = v;
            __syncthreads();

            if (lane < 16) {
                // every warp redundantly computes all 16 gate outputs into its staging slot
                float ghr = red3[lane]      + bhhs[lane];
                float ghz = red3[16 + lane] + bhhs[16 + lane];
                float ghn = red3[32 + lane] + bhhs[32 + lane];
                float r = fsigm(gis[lane] + ghr);
                float z = fsigm(gis[16 + lane] + ghz);
                float n = ftanh(gis[32 + lane] + r * ghn);
                float hp = hbuf[cur][rank * 16 + lane];
                float hn_ = (1.0f - z) * n + z * hp;
                stg[cur][w * 16 + lane] = hn_;
                if (w == 0)
                    Out[(size_t)t * 512 + col * 256 + rank * 16 + lane] = hn_;
            }
            __syncwarp();
            if (!last && lane == 0) {
                fence_proxy_async_cta();
                uint32_t src = cur ? srcS1 : srcS0;
                bulk_c2c(cur ? dstA0 : dstA1, src, 64u, rma);
                if (w >= 8) bulk_c2c(cur ? dstB0 : dstB1, src, 64u, rmb2);
            }
            if (w == 0 && (t & (CHUNK - 1)) == (CHUNK - 1)) {
                __syncwarp();
                if (lane == 0) {
                    membar_gpu();
                    atomicAdd(&outFlag[t >> CSHIFT], 1);
                }
            }
            if (!last) mbar_wait_parity(mb, (uint32_t)(t & 1));
        }
    } else if (bid < NRECUR + NWORK1) {
        // ================= Gi1 worker: Gi1 = Wih1 @ O0 (K=512), chunked =================
        int ww = bid - NRECUR;            // 0..23
        int cellb = ww / 12;              // 0=f 1=b
        int nt = ww % 12;
        const float* W   = cellb ? Wih1b : Wih1f;
        const float* bih = cellb ? bih1b : bih1f;
        float* Gi        = cellb ? g_Gi1B : g_Gi1F;

        int ty = tid >> 4, tx = tid & 15;
        int lr = tid >> 2;
        int kc = (tid & 3) * 8;
        bool act = tid < 256;

        for (int k = 0; k < NCHUNK; k++) {
            if (tid == 0) {
                while (ld_acq_gpu(&g_L0flag[k]) < 32) __nanosleep(128);
            }
            __syncthreads();

            int m0 = k * CHUNK;
            int n0 = nt * 64;
            const float* arow = g_O0 + (size_t)(m0 + (act ? lr : 0)) * 512;
            const float* brow = W + (size_t)(n0 + (act ? lr : 0)) * 512;

            float acc[4][4] = {};
            for (int k0 = 0; k0 < 512; k0 += 32) {
                float4 a0, a1, b0, b1;
                if (act) {
                    a0 = *(const float4*)(arow + k0 + kc);
                    a1 = *(const float4*)(arow + k0 + kc + 4);
                    b0 = *(const float4*)(brow + k0 + kc);
                    b1 = *(const float4*)(brow + k0 + kc + 4);
                }
                __syncthreads();
                if (act) {
                    As[kc+0][lr]=a0.x; As[kc+1][lr]=a0.y; As[kc+2][lr]=a0.z; As[kc+3][lr]=a0.w;
                    As[kc+4][lr]=a1.x; As[kc+5][lr]=a1.y; As[kc+6][lr]=a1.z; As[kc+7][lr]=a1.w;
                    Bs[kc+0][lr]=b0.x; Bs[kc+1][lr]=b0.y; Bs[kc+2][lr]=b0.z; Bs[kc+3][lr]=b0.w;
                    Bs[kc+4][lr]=b1.x; Bs[kc+5][lr]=b1.y; Bs[kc+6][lr]=b1.z; Bs[kc+7][lr]=b1.w;
                }
                __syncthreads();
                if (act) {
#pragma unroll
                    for (int kk = 0; kk < 32; kk++) {
                        float4 av = *(const float4*)&As[kk][ty * 4];
                        float4 bv = *(const float4*)&Bs[kk][tx * 4];
                        float a4[4] = {av.x, av.y, av.z, av.w};
                        float b4[4] = {bv.x, bv.y, bv.z, bv.w};
#pragma unroll
                        for (int i = 0; i < 4; i++)
#pragma unroll
                            for (int j = 0; j < 4; j++)
                                acc[i][j] += a4[i] * b4[j];
                    }
                }
            }
            if (act) {
#pragma unroll
                for (int i = 0; i < 4; i++) {
                    int m = m0 + ty * 4 + i;
#pragma unroll
                    for (int j = 0; j < 4; j++) {
                        int n = n0 + tx * 4 + j;
                        Gi[(size_t)m * G3 + n] = acc[i][j] + bih[n];
                    }
                }
            }
            __syncthreads();
            if (tid == 0) {
                membar_gpu();
                atomicAdd(&g_Gflag[k], 1);
            }
        }
    } else if (bid < NRECUR + NWORK1 + NWORK0) {
        // ================= Gi0 worker: Gi0 = Wih0 @ emb[x] (K=256), chunked, no wait =================
        int ww = bid - NRECUR - NWORK1;   // 0..23
        int cellb = ww / 12;              // 0=f 1=b
        int nt = ww % 12;
        const float* W   = cellb ? Wih0b : Wih0f;
        const float* bih = cellb ? bih0b : bih0f;
        float* Gi        = cellb ? g_GiB : g_GiF;

        int ty = tid >> 4, tx = tid & 15;
        int lr = tid >> 2;
        int kc = (tid & 3) * 8;
        bool act = tid < 256;

        for (int k = 0; k < NCHUNK; k++) {
            int m0 = k * CHUNK;
            int n0 = nt * 64;
            const float* arow = act ? (emb + (size_t)x[m0 + lr] * 256) : emb;
            const float* brow = W + (size_t)(n0 + (act ? lr : 0)) * 256;

            float acc[4][4] = {};
            for (int k0 = 0; k0 < 256; k0 += 32) {
                float4 a0, a1, b0, b1;
                if (act) {
                    a0 = *(const float4*)(arow + k0 + kc);
                    a1 = *(const float4*)(arow + k0 + kc + 4);
                    b0 = *(const float4*)(brow + k0 + kc);
                    b1 = *(const float4*)(brow + k0 + kc + 4);
                }
                __syncthreads();
                if (act) {
                    As[kc+0][lr]=a0.x; As[kc+1][lr]=a0.y; As[kc+2][lr]=a0.z; As[kc+3][lr]=a0.w;
                    As[kc+4][lr]=a1.x; As[kc+5][lr]=a1.y; As[kc+6][lr]=a1.z; As[kc+7][lr]=a1.w;
                    Bs[kc+0][lr]=b0.x; Bs[kc+1][lr]=b0.y; Bs[kc+2][lr]=b0.z; Bs[kc+3][lr]=b0.w;
                    Bs[kc+4][lr]=b1.x; Bs[kc+5][lr]=b1.y; Bs[kc+6][lr]=b1.z; Bs[kc+7][lr]=b1.w;
                }
                __syncthreads();
                if (act) {
#pragma unroll
                    for (int kk = 0; kk < 32; kk++) {
                        float4 av = *(const float4*)&As[kk][ty * 4];
                        float4 bv = *(const float4*)&Bs[kk][tx * 4];
                        float a4[4] = {av.x, av.y, av.z, av.w};
                        float b4[4] = {bv.x, bv.y, bv.z, bv.w};
#pragma unroll
                        for (int i = 0; i < 4; i++)
#pragma unroll
                            for (int j = 0; j < 4; j++)
                                acc[i][j] += a4[i] * b4[j];
                    }
                }
            }
            if (act) {
#pragma unroll
                for (int i = 0; i < 4; i++) {
                    int m = m0 + ty * 4 + i;
#pragma unroll
                    for (int j = 0; j < 4; j++) {
                        int n = n0 + tx * 4 + j;
                        Gi[(size_t)m * G3 + n] = acc[i][j] + bih[n];
                    }
                }
            }
            __syncthreads();
            if (tid == 0) {
                membar_gpu();
                atomicAdd(&g_G0flag[k], 1);
            }
        }
    } else if (bid < NRECUR + NWORK1 + NWORK0 + NEO) {
        // ================= EO worker: log_softmax(H1 rows), chunked =================
        int eo = bid - NRECUR - NWORK1 - NWORK0;  // 0..3
        int w = tid >> 5, lane = tid & 31;

        for (int k = 0; k < NCHUNK; k++) {
            if (tid == 0) {
                while (ld_acq_gpu(&g_H1flag[k]) < 32) __nanosleep(128);
            }
            __syncthreads();

            int base = k * CHUNK + eo * 16;
            for (int rr = w; rr < 16; rr += 12) {
                int row = base + rr;
                const float4* hr = (const float4*)(g_H1 + (size_t)row * 512);
                float4 v[4];
#pragma unroll
                for (int i = 0; i < 4; i++) v[i] = hr[lane + i * 32];
                float m = -1e30f;
#pragma unroll
                for (int i = 0; i < 4; i++)
                    m = fmaxf(m, fmaxf(fmaxf(v[i].x, v[i].y), fmaxf(v[i].z, v[i].w)));
                m = wred_max(m);
                float s = 0.f;
#pragma unroll
                for (int i = 0; i < 4; i++)
                    s += expf(v[i].x - m) + expf(v[i].y - m) + expf(v[i].z - m) + expf(v[i].w - m);
                s = wred_sum(s);
                float lg = m + logf(s);
                float4* er = (float4*)(g_EO + (size_t)row * 512);
#pragma unroll
                for (int i = 0; i < 4; i++) {
                    float4 o4 = {v[i].x - lg, v[i].y - lg, v[i].z - lg, v[i].w - lg};
                    er[lane + i * 32] = o4;
                }
            }
            __syncthreads();
        }
    }
    // pad CTAs (bid >= 116) fall through and exit
}

// ================= decoder stage kernels (tag-batched, wide) =================

__global__ void dec_attn_kernel(const float* __restrict__ de_emb,
                                const float* __restrict__ attn_W,
                                const float* __restrict__ attn_b)
{
    __shared__ __align__(16) float s_cat[NTAGS][1024];
    int tid = threadIdx.x, lane = tid & 31, w = tid >> 5;

    for (int i = tid; i < NTAGS * 1024; i += 256) {
        int tag = i >> 10, j = i & 1023;
        float v;
        if (j < 512) v = de_emb[tag * 512 + j];
        else {
            int jj = j - 512;
            v = (jj < 256) ? g_O0[(size_t)(LSEQ - 1) * 512 + jj]
                           : g_H1[(size_t)(LSEQ - 1) * 512 + jj];
        }
        s_cat[tag][j] = v;
    }
    __syncthreads();

    for (int r = 0; r < 2; r++) {
        int m = blockIdx.x * 16 + w * 2 + r;
        const float4* wr = (const float4*)(attn_W + (size_t)m * 1024);
        float acc[NTAGS] = {};
#pragma unroll
        for (int i = 0; i < 8; i++) {
            float4 wv = wr[lane + i * 32];
#pragma unroll
            for (int tg = 0; tg < NTAGS; tg++) {
                float4 cv = *(const float4*)&s_cat[tg][(lane + i * 32) * 4];
                acc[tg] += wv.x * cv.x + wv.y * cv.y + wv.z * cv.z + wv.w * cv.w;
            }
        }
#pragma unroll
        for (int tg = 0; tg < NTAGS; tg++) {
            float a = wred_sum(acc[tg]);
            if (lane == 0) g_awl[tg * 1024 + m] = a + attn_b[m];
        }
    }
}

// ctx partials with inline softmax normalization
__global__ void dec_ctx_kernel()
{
    __shared__ float p6[NTAGS][64];
    __shared__ float sMx[NTAGS], sSx[NTAGS];
    int ts = blockIdx.x, tid = threadIdx.x, lane = tid & 31, w = tid >> 5;
    int t0 = ts * 64;

    if (w < NTAGS) {
        const float4* ar = (const float4*)(g_awl + w * 1024);
        float4 v[8];
#pragma unroll
        for (int i = 0; i < 8; i++) v[i] = ar[lane + i * 32];
        float m = -1e30f;
#pragma unroll
        for (int i = 0; i < 8; i++)
            m = fmaxf(m, fmaxf(fmaxf(v[i].x, v[i].y), fmaxf(v[i].z, v[i].w)));
        m = wred_max(m);
        float s = 0.f;
#pragma unroll
        for (int i = 0; i < 8; i++)
            s += expf(v[i].x - m) + expf(v[i].y - m) + expf(v[i].z - m) + expf(v[i].w - m);
        s = wred_sum(s);
        if (lane == 0) { sMx[w] = m; sSx[w] = s; }
    }
    __syncthreads();

    for (int i = tid; i < NTAGS * 64; i += 256) {
        int tag = i >> 6, tt = i & 63;
        p6[tag][tt] = expf(g_awl[tag * 1024 + t0 + tt] - sMx[tag]) / sSx[tag];
    }
    __syncthreads();

    int j0 = tid * 2;
    float acc[NTAGS][2] = {};
    for (int tt = 0; tt < 64; tt++) {
        float2 e = *(const float2*)(g_EO + (size_t)(t0 + tt) * 512 + j0);
#pragma unroll
        for (int tg = 0; tg < NTAGS; tg++) {
            float p = p6[tg][tt];
            acc[tg][0] += p * e.x;
            acc[tg][1] += p * e.y;
        }
    }
#pragma unroll
    for (int tg = 0; tg < NTAGS; tg++) {
        g_ctxp[(ts * NTAGS + tg) * 512 + j0]     = acc[tg][0];
        g_ctxp[(ts * NTAGS + tg) * 512 + j0 + 1] = acc[tg][1];
    }
}

__global__ void dec_cat2_kernel(const float* __restrict__ de_emb)
{
    int tag = blockIdx.x, tid = threadIdx.x;
    for (int j = tid; j < 512; j += 256) g_cat2[tag * 1024 + j] = de_emb[tag * 512 + j];
    for (int j = tid; j < 512; j += 256) {
        float s = 0.f;
#pragma unroll
        for (int ts = 0; ts < 16; ts++) s += g_ctxp[(ts * NTAGS + tag) * 512 + j];
        g_cat2[tag * 1024 + 512 + j] = s;
    }
}

__global__ void dec_comb_kernel(const float* __restrict__ comb_W,
                                const float* __restrict__ comb_b)
{
    __shared__ __align__(16) float s_cat[NTAGS][1024];
    int tid = threadIdx.x, lane = tid & 31, w = tid >> 5;
    for (int i = tid; i < NTAGS * 1024; i += 256) s_cat[i >> 10][i & 1023] = g_cat2[i];
    __syncthreads();

    for (int r = 0; r < 2; r++) {
        int m = blockIdx.x * 16 + w * 2 + r;
        const float4* wr = (const float4*)(comb_W + (size_t)m * 1024);
        float acc[NTAGS] = {};
#pragma unroll
        for (int i = 0; i < 8; i++) {
            float4 wv = wr[lane + i * 32];
#pragma unroll
            for (int tg = 0; tg < NTAGS; tg++) {
                float4 cv = *(const float4*)&s_cat[tg][(lane + i * 32) * 4];
                acc[tg] += wv.x * cv.x + wv.y * cv.y + wv.z * cv.z + wv.w * cv.w;
            }
        }
#pragma unroll
        for (int tg = 0; tg < NTAGS; tg++) {
            float a = wred_sum(acc[tg]);
            if (lane == 0) g_oo[tg * 512 + m] = fmaxf(a + comb_b[m], 0.f);
        }
    }
}

__global__ void dec_gates_kernel(const float* __restrict__ de_Wih,
                                 const float* __restrict__ de_Whh,
                                 const float* __restrict__ de_bih,
                                 const float* __restrict__ de_bhh)
{
    __shared__ __align__(16) float s_o[NTAGS][512];
    __shared__ __align__(16) float s_dh[512];
    int tid = threadIdx.x, lane = tid & 31, w = tid >> 5;
    for (int i = tid; i < NTAGS * 512; i += 256) s_o[i >> 9][i & 511] = g_oo[i];
    for (int i = tid; i < 512; i += 256)
        s_dh[i] = (i < 256) ? g_O0[(size_t)(LSEQ - 1) * 512 + i]
                            : g_H1[(size_t)(LSEQ - 1) * 512 + i];
    __syncthreads();

    int wg = blockIdx.x * 8 + w;   // 0..767
    for (int r = 0; r < 4; r++) {
        int job = wg * 4 + r;      // 0..3071
        if (job < 1536) {
            const float4* wr = (const float4*)(de_Whh + (size_t)job * 512);
            float acc = 0.f;
#pragma unroll
            for (int i = 0; i < 4; i++) {
                float4 wv = wr[lane + i * 32];
                float4 cv = *(const float4*)&s_dh[(lane + i * 32) * 4];
                acc += wv.x * cv.x + wv.y * cv.y + wv.z * cv.z + wv.w * cv.w;
            }
            acc = wred_sum(acc);
            if (lane == 0) g_gh[job] = acc + de_bhh[job];
        } else {
            int m = job - 1536;
            const float4* wr = (const float4*)(de_Wih + (size_t)m * 512);
            float acc[NTAGS] = {};
#pragma unroll
            for (int i = 0; i < 4; i++) {
                float4 wv = wr[lane + i * 32];
#pragma unroll
                for (int tg = 0; tg < NTAGS; tg++) {
                    float4 cv = *(const float4*)&s_o[tg][(lane + i * 32) * 4];
                    acc[tg] += wv.x * cv.x + wv.y * cv.y + wv.z * cv.z + wv.w * cv.w;
                }
            }
#pragma unroll
            for (int tg = 0; tg < NTAGS; tg++) {
                float a = wred_sum(acc[tg]);
                if (lane == 0) g_gi[tg * 1536 + m] = a + de_bih[m];
            }
        }
    }
}

__global__ void dec_final_kernel(const float* __restrict__ h2t_W,
                                 const float* __restrict__ h2t_b,
                                 float* __restrict__ out)
{
    __shared__ __align__(16) float s_hn[NTAGS][512];
    __shared__ __align__(16) float s_dh[512];
    __shared__ float s_lg[NTAGS][NTAGS];
    __shared__ float s_rowsum[NTAGS], s_val[NTAGS], s_b[NTAGS];
    __shared__ int   s_seq[8];
    __shared__ int   s_tail, s_per;

    int tid = threadIdx.x, lane = tid & 31, w = tid >> 5;

    if (tid < 512)
        s_dh[tid] = (tid < 256) ? g_O0[(size_t)(LSEQ - 1) * 512 + tid]
                                : g_H1[(size_t)(LSEQ - 1) * 512 + tid];
    __syncthreads();

    for (int idx = tid; idx < NTAGS * 512; idx += 1024) {
        int tag = idx >> 9, j = idx & 511;
        float gir = g_gi[tag * 1536 + j],        ghr = g_gh[j];
        float giz = g_gi[tag * 1536 + 512 + j],  ghz = g_gh[512 + j];
        float gin = g_gi[tag * 1536 + 1024 + j], ghn = g_gh[1024 + j];
        float r = sigm(gir + ghr);
        float z = sigm(giz + ghz);
        float n = tanhf(gin + r * ghn);
        s_hn[tag][j] = (1.0f - z) * n + z * s_dh[j];
    }
    __syncthreads();

    for (int job = w; job < 42; job += 32) {
        if (job < 36) {
            int tag = job / NTAGS, k = job % NTAGS;
            const float4* wr = (const float4*)(h2t_W + (size_t)k * 512);
            float acc = 0.f;
#pragma unroll
            for (int i = 0; i < 4; i++) {
                float4 wv = wr[lane + i * 32];
                float4 cv = *(const float4*)&s_hn[tag][(lane + i * 32) * 4];
                acc += wv.x * cv.x + wv.y * cv.y + wv.z * cv.z + wv.w * cv.w;
            }
            acc = wred_sum(acc);
            if (lane == 0) s_lg[tag][k] = acc + h2t_b[k];
        } else {
            int k = job - 36;
            float acc = 0.f;
            for (int i = lane; i < 512; i += 32) acc += h2t_W[(size_t)k * 512 + i];
            acc = wred_sum(acc);
            if (lane == 0) { s_rowsum[k] = acc; s_b[k] = h2t_b[k]; }
        }
    }
    __syncthreads();

    if (tid == 0) {
        int nxt[NTAGS];
        for (int tg = 0; tg < NTAGS; tg++) {
            float mx = s_lg[tg][0]; int am = 0;
            for (int i = 1; i < NTAGS; i++)
                if (s_lg[tg][i] > mx) { mx = s_lg[tg][i]; am = i; }
            float se = 0.f;
            for (int i = 0; i < NTAGS; i++) se += expf(s_lg[tg][i] - mx);
            s_val[tg] = s_lg[tg][0] - mx - logf(se);
            nxt[tg] = am;
        }
        int s = START_TAG;
        int seq[8];
        for (int i = 0; i < 8; i++) { seq[i] = s; s_seq[i] = s; s = nxt[s]; }
        int tail = 0, per = 1;
        bool found = false;
        for (int k = 1; k < 8 && !found; k++)
            for (int j = 0; j < k; j++)
                if (seq[k] == seq[j]) { tail = j; per = k - j; found = true; break; }
        s_tail = tail; s_per = per;
    }
    __syncthreads();

    int i = tid;
    int st = (i < s_tail) ? s_seq[i] : s_seq[s_tail + (i - s_tail) % s_per];
    float c = s_val[st];
#pragma unroll
    for (int t = 0; t < NTAGS; t++)
        out[(size_t)i * NTAGS + t] = c * s_rowsum[t] + s_b[t];
}

// ---------------- host ----------------
extern "C" void kernel_launch(void* const* d_in, const int* in_sizes, int n_in,
                              void* d_out, int out_size)
{
    const int*   x       = (const int*)  d_in[0];
    const float* emb     = (const float*)d_in[1];
    const float* Wih0f   = (const float*)d_in[2];
    const float* Whh0f   = (const float*)d_in[3];
    const float* bih0f   = (const float*)d_in[4];
    const float* bhh0f   = (const float*)d_in[5];
    const float* Wih0b   = (const float*)d_in[6];
    const float* Whh0b   = (const float*)d_in[7];
    const float* bih0b   = (const float*)d_in[8];
    const float* bhh0b   = (const float*)d_in[9];
    const float* Wih1f   = (const float*)d_in[10];
    const float* Whh1f   = (const float*)d_in[11];
    const float* bih1f   = (const float*)d_in[12];
    const float* bhh1f   = (const float*)d_in[13];
    const float* Wih1b   = (const float*)d_in[14];
    const float* Whh1b   = (const float*)d_in[15];
    const float* bih1b   = (const float*)d_in[16];
    const float* bhh1b   = (const float*)d_in[17];
    const float* ehid0   = (const float*)d_in[18];
    const float* de_emb  = (const float*)d_in[19];
    const float* attn_W  = (const float*)d_in[20];
    const float* attn_b  = (const float*)d_in[21];
    const float* comb_W  = (const float*)d_in[22];
    const float* comb_b  = (const float*)d_in[23];
    const float* de_Wih  = (const float*)d_in[24];
    const float* de_Whh  = (const float*)d_in[25];
    const float* de_bih  = (const float*)d_in[26];
    const float* de_bhh  = (const float*)d_in[27];
    const float* h2t_W   = (const float*)d_in[28];
    const float* h2t_b   = (const float*)d_in[29];
    float* out = (float*)d_out;

    cudaFuncSetAttribute(fused_kernel, cudaFuncAttributeNonPortableClusterSizeAllowed, 1);

    init_flags_kernel<<<1, 64>>>();
    fused_kernel<<<GRID_TOTAL, 384>>>(Whh0f, bhh0f, Whh0b, bhh0b,
                                      Whh1f, bhh1f, Whh1b, bhh1b,
                                      Wih1f, bih1f, Wih1b, bih1b,
                                      Wih0f, bih0f, Wih0b, bih0b,
                                      x, emb, ehid0);
    dec_attn_kernel<<<64, 256>>>(de_emb, attn_W, attn_b);
    dec_ctx_kernel<<<16, 256>>>();
    dec_cat2_kernel<<<NTAGS, 256>>>(de_emb);
    dec_comb_kernel<<<32, 256>>>(comb_W, comb_b);
    dec_gates_kernel<<<96, 256>>>(de_Wih, de_Whh, de_bih, de_bhh);
    dec_final_kernel<<<1, 1024>>>(h2t_W, h2t_b, out);

    (void)in_sizes; (void)n_in; (void)out_size;
}

// round 16
// speedup vs baseline: 1.0861x; 1.0861x over previous
#include <cuda_runtime.h>
#include <cstdint>
#include <math.h>

// Problem dims
#define LSEQ   1024
#define G3     768        // 3*OUT_H
#define HID    256        // OUT_H
#define NTAGS  6
#define CLN    16         // cluster size per cell
#define START_TAG 4
#define CHUNK  32
#define CSHIFT 5
#define NCHUNK (LSEQ / CHUNK)
#define NWORK1 24         // Gi1 GEMM worker CTAs
#define NWORK0 24         // Gi0 GEMM worker CTAs
#define NEO    4          // log_softmax worker CTAs
#define NRECUR 64         // 4 cells x 16 CTAs
#define GRID_TOTAL 128    // 64 + 24 + 24 + 4 = 116, padded to multiple of CLN

// ---------------- scratch (device globals; no allocation) ----------------
__device__ __align__(16) float g_GiF [LSEQ * G3];
__device__ __align__(16) float g_GiB [LSEQ * G3];
__device__ __align__(16) float g_Gi1F[LSEQ * G3];
__device__ __align__(16) float g_Gi1B[LSEQ * G3];
__device__ __align__(16) float g_O0 [LSEQ * 512];
__device__ __align__(16) float g_H1 [LSEQ * 512];
__device__ __align__(16) float g_EO [LSEQ * 512];
__device__ int   g_G0flag[NCHUNK];   // counts to NWORK0 (Gi0 tiles ready)
__device__ int   g_L0flag[NCHUNK];   // counts to 32 (L0 CTAs done with chunk)
__device__ int   g_Gflag [NCHUNK];   // counts to NWORK1 (Gi1 tiles ready)
__device__ int   g_H1flag[NCHUNK];   // counts to 32 (L1 CTAs done with chunk)
// decoder staging
__device__ __align__(16) float g_awl [NTAGS * 1024];
__device__ float g_Mx[NTAGS], g_Sx[NTAGS];
__device__ __align__(16) float g_ctxp[16 * NTAGS * 512];
__device__ __align__(16) float g_cat2[NTAGS * 1024];
__device__ __align__(16) float g_oo  [NTAGS * 512];
__device__ __align__(16) float g_gi  [NTAGS * 1536];
__device__ __align__(16) float g_gh  [1536];

// ---------------- helpers ----------------
__device__ __forceinline__ float wred_sum(float v) {
#pragma unroll
    for (int o = 16; o; o >>= 1) v += __shfl_xor_sync(0xffffffffu, v, o);
    return v;
}
__device__ __forceinline__ float wred_max(float v) {
#pragma unroll
    for (int o = 16; o; o >>= 1) v = fmaxf(v, __shfl_xor_sync(0xffffffffu, v, o));
    return v;
}
__device__ __forceinline__ float sigm(float x) { return 1.0f / (1.0f + expf(-x)); }
__device__ __forceinline__ float fsigm(float x) { return __fdividef(1.0f, 1.0f + __expf(-x)); }
__device__ __forceinline__ float ftanh(float x) {
    return 1.0f - __fdividef(2.0f, __expf(2.0f * x) + 1.0f);
}
__device__ __forceinline__ void cluster_sync_asm() {
    asm volatile("barrier.cluster.arrive.aligned;" ::: "memory");
    asm volatile("barrier.cluster.wait.aligned;" ::: "memory");
}
__device__ __forceinline__ uint32_t mapa_sc(uint32_t la, uint32_t r) {
    uint32_t ra;
    asm("mapa.shared::cluster.u32 %0, %1, %2;" : "=r"(ra) : "r"(la), "r"(r));
    return ra;
}
__device__ __forceinline__ void st_async_b32(uint32_t raddr, uint32_t v, uint32_t rmbar) {
    asm volatile("st.async.weak.shared::cluster.mbarrier::complete_tx::bytes.b32 [%0], %1, [%2];"
                 :: "r"(raddr), "r"(v), "r"(rmbar) : "memory");
}
__device__ __forceinline__ void mbar_init(uint32_t mb, uint32_t cnt) {
    asm volatile("mbarrier.init.shared.b64 [%0], %1;" :: "r"(mb), "r"(cnt) : "memory");
}
__device__ __forceinline__ void mbar_arrive_expect(uint32_t mb, uint32_t bytes) {
    asm volatile("mbarrier.arrive.expect_tx.shared.b64 _, [%0], %1;" :: "r"(mb), "r"(bytes) : "memory");
}
__device__ __forceinline__ void mbar_wait_parity(uint32_t mb, uint32_t parity) {
    uint32_t done;
    asm volatile(
        "{\n\t.reg .pred p;\n\t"
        "mbarrier.try_wait.parity.acquire.cluster.shared::cta.b64 p, [%1], %2;\n\t"
        "selp.b32 %0, 1, 0, p;\n\t}"
        : "=r"(done) : "r"(mb), "r"(parity) : "memory");
    if (!done) {
        asm volatile(
            "{\n\t.reg .pred P1;\n\t"
            "WL_%=:\n\t"
            "mbarrier.try_wait.parity.acquire.cluster.shared::cta.b64 P1, [%0], %1, 0x989680;\n\t"
            "@P1 bra.uni WD_%=;\n\t"
            "bra.uni WL_%=;\n\t"
            "WD_%=:\n\t}"
            :: "r"(mb), "r"(parity) : "memory");
    }
}
__device__ __forceinline__ int ld_acq_gpu(const int* p) {
    int v;
    asm volatile("ld.acquire.gpu.global.b32 %0, [%1];" : "=r"(v) : "l"(p) : "memory");
    return v;
}
__device__ __forceinline__ void membar_gpu() {
    asm volatile("membar.gl;" ::: "memory");
}

// ---------------- flag init ----------------
__global__ void init_flags_kernel()
{
    int i = threadIdx.x;
    if (i < NCHUNK) {
        g_G0flag[i] = 0;
        g_L0flag[i] = 0;
        g_Gflag[i]  = 0;
        g_H1flag[i] = 0;
    }
}

// ---------------- fused pipelined encoder (R9 protocol, CHUNK=32) ----------------
// bid 0-63:    4 clusters of 16 = cells L0f, L0b, L1f, L1b (recurrence)
// bid 64-87:   24 Gi1 workers (BM=32 tile, wait L0flag)
// bid 88-111:  24 Gi0 workers (BM=32 tile, no wait)
// bid 112-115: 4 EO workers (log_softmax rows, wait H1flag)
// bid 116-127: pad, exit
__global__ void __cluster_dims__(CLN, 1, 1) fused_kernel(
    const float* __restrict__ Whh0f, const float* __restrict__ bhh0f,
    const float* __restrict__ Whh0b, const float* __restrict__ bhh0b,
    const float* __restrict__ Whh1f, const float* __restrict__ bhh1f,
    const float* __restrict__ Whh1b, const float* __restrict__ bhh1b,
    const float* __restrict__ Wih1f, const float* __restrict__ bih1f,
    const float* __restrict__ Wih1b, const float* __restrict__ bih1b,
    const float* __restrict__ Wih0f, const float* __restrict__ bih0f,
    const float* __restrict__ Wih0b, const float* __restrict__ bih0b,
    const int*   __restrict__ x,     const float* __restrict__ emb,
    const float* __restrict__ hinit)
{
    __shared__ __align__(16) float hbuf[2][256];
    __shared__ __align__(16) float red3[48];
    __shared__ __align__(16) float gis[48];
    __shared__ __align__(16) float bhhs[48];
    __shared__ __align__(16) float As[32][68];
    __shared__ __align__(16) float Bs[32][68];
    __shared__ __align__(8)  uint64_t s_mb;

    int bid = blockIdx.x;
    int tid = threadIdx.x;

    if (bid < NRECUR) {
        // ================= recurrence cell =================
        int cell = bid >> 4;          // 0=L0f 1=L0b 2=L1f 3=L1b
        int isL1 = cell >> 1;
        int col  = cell & 1;
        unsigned rank;
        asm("mov.u32 %0, %%cluster_ctarank;" : "=r"(rank));

        const float* Gi  = isL1 ? (col ? g_Gi1B : g_Gi1F) : (col ? g_GiB : g_GiF);
        const float* Whh = (cell == 0) ? Whh0f : (cell == 1) ? Whh0b : (cell == 2) ? Whh1f : Whh1b;
        const float* bhh = (cell == 0) ? bhh0f : (cell == 1) ? bhh0b : (cell == 2) ? bhh1f : bhh1b;
        float* Out       = isL1 ? g_H1 : g_O0;
        const int* inFlag = isL1 ? g_Gflag : g_G0flag;
        int inTarget      = isL1 ? NWORK1 : NWORK0;
        int* outFlag      = isL1 ? g_H1flag : g_L0flag;

        int q  = tid & 7;             // K-chunk of 32
        int rl = tid >> 3;            // 0..47  (gate-row local)
        int g  = rl >> 4, jj = rl & 15;
        int rowGlobal = g * 256 + (int)rank * 16 + jj;
        int w    = tid >> 5;
        int lane = tid & 31;

        // weights loaded in q-rotated order so the h-read is bank-conflict-free
        float4 w4[8];
        const float* wp = Whh + (size_t)rowGlobal * 256 + q * 32;
#pragma unroll
        for (int i = 0; i < 8; i++) {
            int ii = (i + q) & 7;
            w4[i] = *(const float4*)(wp + ii * 4);
        }

        uint32_t mb = (uint32_t)__cvta_generic_to_shared(&s_mb);
        if (tid == 0) mbar_init(mb, 1);
        if (tid < 256) hbuf[0][tid] = hinit[cell * 256 + tid];
        if (tid < 48)  bhhs[tid] = bhh[(tid >> 4) * 256 + (int)rank * 16 + (tid & 15)];
        __syncthreads();
        cluster_sync_asm();

        // remote addresses. warp w -> dest w; warps 8-11 also -> dest w+4.
        uint32_t ra0a = 0, ra1a = 0, rma = 0, ra0b = 0, ra1b = 0, rmb2 = 0;
        {
            uint32_t la0 = (uint32_t)__cvta_generic_to_shared(&hbuf[0][rank * 16 + lane]);
            uint32_t la1 = (uint32_t)__cvta_generic_to_shared(&hbuf[1][rank * 16 + lane]);
            ra0a = mapa_sc(la0, (uint32_t)w);
            ra1a = mapa_sc(la1, (uint32_t)w);
            rma  = mapa_sc(mb,  (uint32_t)w);
            if (w >= 8) {
                ra0b = mapa_sc(la0, (uint32_t)(w + 4));
                ra1b = mapa_sc(la1, (uint32_t)(w + 4));
                rmb2 = mapa_sc(mb,  (uint32_t)(w + 4));
            }
        }

        float gi_cur = 0.f;

        for (int t = 0; t < LSEQ; t++) {
            int cur = t & 1;
            bool last = (t == LSEQ - 1);

            if ((t & (CHUNK - 1)) == 0) {
                if (tid == 0) {
                    int k = t >> CSHIFT;
                    while (ld_acq_gpu(&inFlag[k]) < inTarget) __nanosleep(128);
                }
                __syncthreads();
                if (tid < 48) gi_cur = Gi[(size_t)t * G3 + (tid >> 4) * 256 + (int)rank * 16 + (tid & 15)];
            }

            if (!last && tid == 0) mbar_arrive_expect(mb, 1024);
            if (tid < 48) {
                gis[tid] = gi_cur;
                bool pf = (t + 1 < LSEQ) && (((t + 1) & (CHUNK - 1)) != 0);
                if (pf) gi_cur = Gi[(size_t)(t + 1) * G3 + (tid >> 4) * 256 + (int)rank * 16 + (tid & 15)];
            }

            const float* hc = hbuf[cur] + q * 32;
            float ax = 0.f, ay = 0.f, az = 0.f, aw = 0.f;
#pragma unroll
            for (int i = 0; i < 8; i++) {
                int ii = (i + q) & 7;
                float4 hv = *(const float4*)(hc + ii * 4);
                ax += w4[i].x * hv.x; ay += w4[i].y * hv.y;
                az += w4[i].z * hv.z; aw += w4[i].w * hv.w;
            }
            float v = (ax + ay) + (az + aw);
            v += __shfl_xor_sync(0xffffffffu, v, 1);
            v += __shfl_xor_sync(0xffffffffu, v, 2);
            v += __shfl_xor_sync(0xffffffffu, v, 4);
            if (q == 0) red3[rl] = v;
            __syncthreads();

            if (lane < 16) {
                float ghr = red3[lane]      + bhhs[lane];
                float ghz = red3[16 + lane] + bhhs[16 + lane];
                float ghn = red3[32 + lane] + bhhs[32 + lane];
                float r = fsigm(gis[lane] + ghr);
                float z = fsigm(gis[16 + lane] + ghz);
                float n = ftanh(gis[32 + lane] + r * ghn);
                float hp = hbuf[cur][rank * 16 + lane];
                float hn_ = (1.0f - z) * n + z * hp;
                uint32_t hv = __float_as_uint(hn_);

                if (!last) {
                    st_async_b32(cur ? ra0a : ra1a, hv, rma);
                    if (w >= 8) st_async_b32(cur ? ra0b : ra1b, hv, rmb2);
                }

                if (w == 0)
                    Out[(size_t)t * 512 + col * 256 + rank * 16 + lane] = hn_;
            }
            if (w == 0 && (t & (CHUNK - 1)) == (CHUNK - 1)) {
                __syncwarp();
                if (lane == 0) {
                    membar_gpu();
                    atomicAdd(&outFlag[t >> CSHIFT], 1);
                }
            }
            if (!last) mbar_wait_parity(mb, (uint32_t)(t & 1));
        }
    } else if (bid < NRECUR + NWORK1) {
        // ================= Gi1 worker: Gi1 = Wih1 @ O0 (K=512), BM=32 chunked =================
        int ww = bid - NRECUR;            // 0..23
        int cellb = ww / 12;              // 0=f 1=b
        int nt = ww % 12;
        const float* W   = cellb ? Wih1b : Wih1f;
        const float* bih = cellb ? bih1b : bih1f;
        float* Gi        = cellb ? g_Gi1B : g_Gi1F;

        bool act = tid < 256;
        int at = act ? tid : 0;
        int ty = at >> 4, tx = at & 15;       // ty: 2 rows each; tx: 4 cols each
        int lrB = at >> 2;                    // 0..63 (B rows)
        int kcB = (at & 3) * 8;
        int lrA = at >> 3;                    // 0..31 (A rows)
        int kcA = (at & 7) * 4;

        for (int k = 0; k < NCHUNK; k++) {
            if (tid == 0) {
                while (ld_acq_gpu(&g_L0flag[k]) < 32) __nanosleep(128);
            }
            __syncthreads();

            int m0 = k * CHUNK;
            int n0 = nt * 64;
            const float* arow = g_O0 + (size_t)(m0 + lrA) * 512;
            const float* brow = W + (size_t)(n0 + lrB) * 512;

            float acc[2][4] = {};
            for (int k0 = 0; k0 < 512; k0 += 32) {
                float4 a0, b0, b1;
                if (act) {
                    a0 = *(const float4*)(arow + k0 + kcA);
                    b0 = *(const float4*)(brow + k0 + kcB);
                    b1 = *(const float4*)(brow + k0 + kcB + 4);
                }
                __syncthreads();
                if (act) {
                    As[kcA+0][lrA]=a0.x; As[kcA+1][lrA]=a0.y; As[kcA+2][lrA]=a0.z; As[kcA+3][lrA]=a0.w;
                    Bs[kcB+0][lrB]=b0.x; Bs[kcB+1][lrB]=b0.y; Bs[kcB+2][lrB]=b0.z; Bs[kcB+3][lrB]=b0.w;
                    Bs[kcB+4][lrB]=b1.x; Bs[kcB+5][lrB]=b1.y; Bs[kcB+6][lrB]=b1.z; Bs[kcB+7][lrB]=b1.w;
                }
                __syncthreads();
                if (act) {
#pragma unroll
                    for (int kk = 0; kk < 32; kk++) {
                        float2 av = *(const float2*)&As[kk][ty * 2];
                        float4 bv = *(const float4*)&Bs[kk][tx * 4];
                        float a2[2] = {av.x, av.y};
                        float b4[4] = {bv.x, bv.y, bv.z, bv.w};
#pragma unroll
                        for (int i = 0; i < 2; i++)
#pragma unroll
                            for (int j = 0; j < 4; j++)
                                acc[i][j] += a2[i] * b4[j];
                    }
                }
            }
            if (act) {
#pragma unroll
                for (int i = 0; i < 2; i++) {
                    int m = m0 + ty * 2 + i;
#pragma unroll
                    for (int j = 0; j < 4; j++) {
                        int n = n0 + tx * 4 + j;
                        Gi[(size_t)m * G3 + n] = acc[i][j] + bih[n];
                    }
                }
            }
            __syncthreads();
            if (tid == 0) {
                membar_gpu();
                atomicAdd(&g_Gflag[k], 1);
            }
        }
    } else if (bid < NRECUR + NWORK1 + NWORK0) {
        // ================= Gi0 worker: Gi0 = Wih0 @ emb[x] (K=256), BM=32, no wait =================
        int ww = bid - NRECUR - NWORK1;   // 0..23
        int cellb = ww / 12;
        int nt = ww % 12;
        const float* W   = cellb ? Wih0b : Wih0f;
        const float* bih = cellb ? bih0b : bih0f;
        float* Gi        = cellb ? g_GiB : g_GiF;

        bool act = tid < 256;
        int at = act ? tid : 0;
        int ty = at >> 4, tx = at & 15;
        int lrB = at >> 2;
        int kcB = (at & 3) * 8;
        int lrA = at >> 3;
        int kcA = (at & 7) * 4;

        for (int k = 0; k < NCHUNK; k++) {
            int m0 = k * CHUNK;
            int n0 = nt * 64;
            const float* arow = emb + (size_t)x[m0 + lrA] * 256;
            const float* brow = W + (size_t)(n0 + lrB) * 256;

            float acc[2][4] = {};
            for (int k0 = 0; k0 < 256; k0 += 32) {
                float4 a0, b0, b1;
                if (act) {
                    a0 = *(const float4*)(arow + k0 + kcA);
                    b0 = *(const float4*)(brow + k0 + kcB);
                    b1 = *(const float4*)(brow + k0 + kcB + 4);
                }
                __syncthreads();
                if (act) {
                    As[kcA+0][lrA]=a0.x; As[kcA+1][lrA]=a0.y; As[kcA+2][lrA]=a0.z; As[kcA+3][lrA]=a0.w;
                    Bs[kcB+0][lrB]=b0.x; Bs[kcB+1][lrB]=b0.y; Bs[kcB+2][lrB]=b0.z; Bs[kcB+3][lrB]=b0.w;
                    Bs[kcB+4][lrB]=b1.x; Bs[kcB+5][lrB]=b1.y; Bs[kcB+6][lrB]=b1.z; Bs[kcB+7][lrB]=b1.w;
                }
                __syncthreads();
                if (act) {
#pragma unroll
                    for (int kk = 0; kk < 32; kk++) {
                        float2 av = *(const float2*)&As[kk][ty * 2];
                        float4 bv = *(const float4*)&Bs[kk][tx * 4];
                        float a2[2] = {av.x, av.y};
                        float b4[4] = {bv.x, bv.y, bv.z, bv.w};
#pragma unroll
                        for (int i = 0; i < 2; i++)
#pragma unroll
                            for (int j = 0; j < 4; j++)
                                acc[i][j] += a2[i] * b4[j];
                    }
                }
            }
            if (act) {
#pragma unroll
                for (int i = 0; i < 2; i++) {
                    int m = m0 + ty * 2 + i;
#pragma unroll
                    for (int j = 0; j < 4; j++) {
                        int n = n0 + tx * 4 + j;
                        Gi[(size_t)m * G3 + n] = acc[i][j] + bih[n];
                    }
                }
            }
            __syncthreads();
            if (tid == 0) {
                membar_gpu();
                atomicAdd(&g_G0flag[k], 1);
            }
        }
    } else if (bid < NRECUR + NWORK1 + NWORK0 + NEO) {
        // ================= EO worker: log_softmax(H1 rows), chunked =================
        int eo = bid - NRECUR - NWORK1 - NWORK0;  // 0..3
        int w = tid >> 5, lane = tid & 31;

        for (int k = 0; k < NCHUNK; k++) {
            if (tid == 0) {
                while (ld_acq_gpu(&g_H1flag[k]) < 32) __nanosleep(128);
            }
            __syncthreads();

            int base = k * CHUNK + eo * 8;   // 8 rows per EO CTA per chunk
            if (w < 8) {
                int row = base + w;
                const float4* hr = (const float4*)(g_H1 + (size_t)row * 512);
                float4 v[4];
#pragma unroll
                for (int i = 0; i < 4; i++) v[i] = hr[lane + i * 32];
                float m = -1e30f;
#pragma unroll
                for (int i = 0; i < 4; i++)
                    m = fmaxf(m, fmaxf(fmaxf(v[i].x, v[i].y), fmaxf(v[i].z, v[i].w)));
                m = wred_max(m);
                float s = 0.f;
#pragma unroll
                for (int i = 0; i < 4; i++)
                    s += expf(v[i].x - m) + expf(v[i].y - m) + expf(v[i].z - m) + expf(v[i].w - m);
                s = wred_sum(s);
                float lg = m + logf(s);
                float4* er = (float4*)(g_EO + (size_t)row * 512);
#pragma unroll
                for (int i = 0; i < 4; i++) {
                    float4 o4 = {v[i].x - lg, v[i].y - lg, v[i].z - lg, v[i].w - lg};
                    er[lane + i * 32] = o4;
                }
            }
            __syncthreads();
        }
    }
    // pad CTAs (bid >= 116) fall through and exit
}

// ================= decoder stage kernels (tag-batched, wide) =================

// grid 128 x 256: 8 rows/CTA, 1 row per warp
__global__ void dec_attn_kernel(const float* __restrict__ de_emb,
                                const float* __restrict__ attn_W,
                                const float* __restrict__ attn_b)
{
    __shared__ __align__(16) float s_cat[NTAGS][1024];
    int tid = threadIdx.x, lane = tid & 31, w = tid >> 5;

    for (int i = tid; i < NTAGS * 1024; i += 256) {
        int tag = i >> 10, j = i & 1023;
        float v;
        if (j < 512) v = de_emb[tag * 512 + j];
        else {
            int jj = j - 512;
            v = (jj < 256) ? g_O0[(size_t)(LSEQ - 1) * 512 + jj]
                           : g_H1[(size_t)(LSEQ - 1) * 512 + jj];
        }
        s_cat[tag][j] = v;
    }
    __syncthreads();

    int m = blockIdx.x * 8 + w;
    const float4* wr = (const float4*)(attn_W + (size_t)m * 1024);
    float acc[NTAGS] = {};
#pragma unroll
    for (int i = 0; i < 8; i++) {
        float4 wv = wr[lane + i * 32];
#pragma unroll
        for (int tg = 0; tg < NTAGS; tg++) {
            float4 cv = *(const float4*)&s_cat[tg][(lane + i * 32) * 4];
            acc[tg] += wv.x * cv.x + wv.y * cv.y + wv.z * cv.z + wv.w * cv.w;
        }
    }
#pragma unroll
    for (int tg = 0; tg < NTAGS; tg++) {
        float a = wred_sum(acc[tg]);
        if (lane == 0) g_awl[tg * 1024 + m] = a + attn_b[m];
    }
}

__global__ void dec_softmax_kernel()
{
    int tag = blockIdx.x, tid = threadIdx.x, lane = tid & 31, w = tid >> 5;
    __shared__ float sr[8];
    float4 v = *(const float4*)(g_awl + tag * 1024 + tid * 4);
    float m = fmaxf(fmaxf(v.x, v.y), fmaxf(v.z, v.w));
    m = wred_max(m);
    if (lane == 0) sr[w] = m;
    __syncthreads();
    if (w == 0) {
        float mm = (lane < 8) ? sr[lane] : -1e30f;
        mm = wred_max(mm);
        if (lane == 0) sr[0] = mm;
    }
    __syncthreads();
    float M = sr[0];
    float s = expf(v.x - M) + expf(v.y - M) + expf(v.z - M) + expf(v.w - M);
    s = wred_sum(s);
    __syncthreads();
    if (lane == 0) sr[w] = s;
    __syncthreads();
    if (tid == 0) {
        float ss = 0.f;
        for (int i = 0; i < 8; i++) ss += sr[i];
        g_Mx[tag] = M;
        g_Sx[tag] = ss;
    }
}

__global__ void dec_ctx_kernel()
{
    __shared__ float p6[NTAGS][64];
    int ts = blockIdx.x, tid = threadIdx.x;
    int t0 = ts * 64;
    for (int i = tid; i < NTAGS * 64; i += 256) {
        int tag = i >> 6, tt = i & 63;
        p6[tag][tt] = expf(g_awl[tag * 1024 + t0 + tt] - g_Mx[tag]) / g_Sx[tag];
    }
    __syncthreads();

    int j0 = tid * 2;
    float acc[NTAGS][2] = {};
    for (int tt = 0; tt < 64; tt++) {
        float2 e = *(const float2*)(g_EO + (size_t)(t0 + tt) * 512 + j0);
#pragma unroll
        for (int tg = 0; tg < NTAGS; tg++) {
            float p = p6[tg][tt];
            acc[tg][0] += p * e.x;
            acc[tg][1] += p * e.y;
        }
    }
#pragma unroll
    for (int tg = 0; tg < NTAGS; tg++) {
        g_ctxp[(ts * NTAGS + tg) * 512 + j0]     = acc[tg][0];
        g_ctxp[(ts * NTAGS + tg) * 512 + j0 + 1] = acc[tg][1];
    }
}

__global__ void dec_cat2_kernel(const float* __restrict__ de_emb)
{
    int tag = blockIdx.x, tid = threadIdx.x;
    for (int j = tid; j < 512; j += 256) g_cat2[tag * 1024 + j] = de_emb[tag * 512 + j];
    for (int j = tid; j < 512; j += 256) {
        float s = 0.f;
#pragma unroll
        for (int ts = 0; ts < 16; ts++) s += g_ctxp[(ts * NTAGS + tag) * 512 + j];
        g_cat2[tag * 1024 + 512 + j] = s;
    }
}

__global__ void dec_comb_kernel(const float* __restrict__ comb_W,
                                const float* __restrict__ comb_b)
{
    __shared__ __align__(16) float s_cat[NTAGS][1024];
    int tid = threadIdx.x, lane = tid & 31, w = tid >> 5;
    for (int i = tid; i < NTAGS * 1024; i += 256) s_cat[i >> 10][i & 1023] = g_cat2[i];
    __syncthreads();

    for (int r = 0; r < 2; r++) {
        int m = blockIdx.x * 16 + w * 2 + r;
        const float4* wr = (const float4*)(comb_W + (size_t)m * 1024);
        float acc[NTAGS] = {};
#pragma unroll
        for (int i = 0; i < 8; i++) {
            float4 wv = wr[lane + i * 32];
#pragma unroll
            for (int tg = 0; tg < NTAGS; tg++) {
                float4 cv = *(const float4*)&s_cat[tg][(lane + i * 32) * 4];
                acc[tg] += wv.x * cv.x + wv.y * cv.y + wv.z * cv.z + wv.w * cv.w;
            }
        }
#pragma unroll
        for (int tg = 0; tg < NTAGS; tg++) {
            float a = wred_sum(acc[tg]);
            if (lane == 0) g_oo[tg * 512 + m] = fmaxf(a + comb_b[m], 0.f);
        }
    }
}

__global__ void dec_gates_kernel(const float* __restrict__ de_Wih,
                                 const float* __restrict__ de_Whh,
                                 const float* __restrict__ de_bih,
                                 const float* __restrict__ de_bhh)
{
    __shared__ __align__(16) float s_o[NTAGS][512];
    __shared__ __align__(16) float s_dh[512];
    int tid = threadIdx.x, lane = tid & 31, w = tid >> 5;
    for (int i = tid; i < NTAGS * 512; i += 256) s_o[i >> 9][i & 511] = g_oo[i];
    for (int i = tid; i < 512; i += 256)
        s_dh[i] = (i < 256) ? g_O0[(size_t)(LSEQ - 1) * 512 + i]
                            : g_H1[(size_t)(LSEQ - 1) * 512 + i];
    __syncthreads();

    int wg = blockIdx.x * 8 + w;   // 0..767
    for (int r = 0; r < 4; r++) {
        int job = wg * 4 + r;      // 0..3071
        if (job < 1536) {
            const float4* wr = (const float4*)(de_Whh + (size_t)job * 512);
            float acc = 0.f;
#pragma unroll
            for (int i = 0; i < 4; i++) {
                float4 wv = wr[lane + i * 32];
                float4 cv = *(const float4*)&s_dh[(lane + i * 32) * 4];
                acc += wv.x * cv.x + wv.y * cv.y + wv.z * cv.z + wv.w * cv.w;
            }
            acc = wred_sum(acc);
            if (lane == 0) g_gh[job] = acc + de_bhh[job];
        } else {
            int m = job - 1536;
            const float4* wr = (const float4*)(de_Wih + (size_t)m * 512);
            float acc[NTAGS] = {};
#pragma unroll
            for (int i = 0; i < 4; i++) {
                float4 wv = wr[lane + i * 32];
#pragma unroll
                for (int tg = 0; tg < NTAGS; tg++) {
                    float4 cv = *(const float4*)&s_o[tg][(lane + i * 32) * 4];
                    acc[tg] += wv.x * cv.x + wv.y * cv.y + wv.z * cv.z + wv.w * cv.w;
                }
            }
#pragma unroll
            for (int tg = 0; tg < NTAGS; tg++) {
                float a = wred_sum(acc[tg]);
                if (lane == 0) g_gi[tg * 1536 + m] = a + de_bih[m];
            }
        }
    }
}

__global__ void dec_final_kernel(const float* __restrict__ h2t_W,
                                 const float* __restrict__ h2t_b,
                                 float* __restrict__ out)
{
    __shared__ __align__(16) float s_hn[NTAGS][512];
    __shared__ __align__(16) float s_dh[512];
    __shared__ float s_lg[NTAGS][NTAGS];
    __shared__ float s_rowsum[NTAGS], s_val[NTAGS], s_b[NTAGS];
    __shared__ int   s_seq[8];
    __shared__ int   s_tail, s_per;

    int tid = threadIdx.x, lane = tid & 31, w = tid >> 5;

    if (tid < 512)
        s_dh[tid] = (tid < 256) ? g_O0[(size_t)(LSEQ - 1) * 512 + tid]
                                : g_H1[(size_t)(LSEQ - 1) * 512 + tid];
    __syncthreads();

    for (int idx = tid; idx < NTAGS * 512; idx += 1024) {
        int tag = idx >> 9, j = idx & 511;
        float gir = g_gi[tag * 1536 + j],        ghr = g_gh[j];
        float giz = g_gi[tag * 1536 + 512 + j],  ghz = g_gh[512 + j];
        float gin = g_gi[tag * 1536 + 1024 + j], ghn = g_gh[1024 + j];
        float r = sigm(gir + ghr);
        float z = sigm(giz + ghz);
        float n = tanhf(gin + r * ghn);
        s_hn[tag][j] = (1.0f - z) * n + z * s_dh[j];
    }
    __syncthreads();

    for (int job = w; job < 42; job += 32) {
        if (job < 36) {
            int tag = job / NTAGS, k = job % NTAGS;
            const float4* wr = (const float4*)(h2t_W + (size_t)k * 512);
            float acc = 0.f;
#pragma unroll
            for (int i = 0; i < 4; i++) {
                float4 wv = wr[lane + i * 32];
                float4 cv = *(const float4*)&s_hn[tag][(lane + i * 32) * 4];
                acc += wv.x * cv.x + wv.y * cv.y + wv.z * cv.z + wv.w * cv.w;
            }
            acc = wred_sum(acc);
            if (lane == 0) s_lg[tag][k] = acc + h2t_b[k];
        } else {
            int k = job - 36;
            float acc = 0.f;
            for (int i = lane; i < 512; i += 32) acc += h2t_W[(size_t)k * 512 + i];
            acc = wred_sum(acc);
            if (lane == 0) { s_rowsum[k] = acc; s_b[k] = h2t_b[k]; }
        }
    }
    __syncthreads();

    if (tid == 0) {
        int nxt[NTAGS];
        for (int tg = 0; tg < NTAGS; tg++) {
            float mx = s_lg[tg][0]; int am = 0;
            for (int i = 1; i < NTAGS; i++)
                if (s_lg[tg][i] > mx) { mx = s_lg[tg][i]; am = i; }
            float se = 0.f;
            for (int i = 0; i < NTAGS; i++) se += expf(s_lg[tg][i] - mx);
            s_val[tg] = s_lg[tg][0] - mx - logf(se);
            nxt[tg] = am;
        }
        int s = START_TAG;
        int seq[8];
        for (int i = 0; i < 8; i++) { seq[i] = s; s_seq[i] = s; s = nxt[s]; }
        int tail = 0, per = 1;
        bool found = false;
        for (int k = 1; k < 8 && !found; k++)
            for (int j = 0; j < k; j++)
                if (seq[k] == seq[j]) { tail = j; per = k - j; found = true; break; }
        s_tail = tail; s_per = per;
    }
    __syncthreads();

    int i = tid;
    int st = (i < s_tail) ? s_seq[i] : s_seq[s_tail + (i - s_tail) % s_per];
    float c = s_val[st];
#pragma unroll
    for (int t = 0; t < NTAGS; t++)
        out[(size_t)i * NTAGS + t] = c * s_rowsum[t] + s_b[t];
}

// ---------------- host ----------------
extern "C" void kernel_launch(void* const* d_in, const int* in_sizes, int n_in,
                              void* d_out, int out_size)
{
    const int*   x       = (const int*)  d_in[0];
    const float* emb     = (const float*)d_in[1];
    const float* Wih0f   = (const float*)d_in[2];
    const float* Whh0f   = (const float*)d_in[3];
    const float* bih0f   = (const float*)d_in[4];
    const float* bhh0f   = (const float*)d_in[5];
    const float* Wih0b   = (const float*)d_in[6];
    const float* Whh0b   = (const float*)d_in[7];
    const float* bih0b   = (const float*)d_in[8];
    const float* bhh0b   = (const float*)d_in[9];
    const float* Wih1f   = (const float*)d_in[10];
    const float* Whh1f   = (const float*)d_in[11];
    const float* bih1f   = (const float*)d_in[12];
    const float* bhh1f   = (const float*)d_in[13];
    const float* Wih1b   = (const float*)d_in[14];
    const float* Whh1b   = (const float*)d_in[15];
    const float* bih1b   = (const float*)d_in[16];
    const float* bhh1b   = (const float*)d_in[17];
    const float* ehid0   = (const float*)d_in[18];
    const float* de_emb  = (const float*)d_in[19];
    const float* attn_W  = (const float*)d_in[20];
    const float* attn_b  = (const float*)d_in[21];
    const float* comb_W  = (const float*)d_in[22];
    const float* comb_b  = (const float*)d_in[23];
    const float* de_Wih  = (const float*)d_in[24];
    const float* de_Whh  = (const float*)d_in[25];
    const float* de_bih  = (const float*)d_in[26];
    const float* de_bhh  = (const float*)d_in[27];
    const float* h2t_W   = (const float*)d_in[28];
    const float* h2t_b   = (const float*)d_in[29];
    float* out = (float*)d_out;

    cudaFuncSetAttribute(fused_kernel, cudaFuncAttributeNonPortableClusterSizeAllowed, 1);

    init_flags_kernel<<<1, 64>>>();
    fused_kernel<<<GRID_TOTAL, 384>>>(Whh0f, bhh0f, Whh0b, bhh0b,
                                      Whh1f, bhh1f, Whh1b, bhh1b,
                                      Wih1f, bih1f, Wih1b, bih1b,
                                      Wih0f, bih0f, Wih0b, bih0b,
                                      x, emb, ehid0);
    dec_attn_kernel<<<128, 256>>>(de_emb, attn_W, attn_b);
    dec_softmax_kernel<<<NTAGS, 256>>>();
    dec_ctx_kernel<<<16, 256>>>();
    dec_cat2_kernel<<<NTAGS, 256>>>(de_emb);
    dec_comb_kernel<<<32, 256>>>(comb_W, comb_b);
    dec_gates_kernel<<<96, 256>>>(de_Wih, de_Whh, de_bih, de_bhh);
    dec_final_kernel<<<1, 1024>>>(h2t_W, h2t_b, out);

    (void)in_sizes; (void)n_in; (void)out_size;
}

// round 17
// speedup vs baseline: 1.0905x; 1.0040x over previous
#include <cuda_runtime.h>
#include <cstdint>
#include <math.h>

// Problem dims
#define LSEQ   1024
#define G3     768        // 3*OUT_H
#define HID    256        // OUT_H
#define NTAGS  6
#define CLN    16         // cluster size per cell
#define START_TAG 4
#define CHUNK  32
#define CSHIFT 5
#define NCHUNK (LSEQ / CHUNK)
#define NWORK1 24         // Gi1 GEMM worker CTAs
#define NWORK0 24         // Gi0 GEMM worker CTAs
#define NEO    4          // log_softmax worker CTAs
#define NRECUR 64         // 4 cells x 16 CTAs
#define GRID_TOTAL 128    // 64 + 24 + 24 + 4 = 116, padded to multiple of CLN

// ---------------- scratch (device globals; no allocation) ----------------
__device__ __align__(16) float g_GiF [LSEQ * G3];
__device__ __align__(16) float g_GiB [LSEQ * G3];
__device__ __align__(16) float g_Gi1F[LSEQ * G3];
__device__ __align__(16) float g_Gi1B[LSEQ * G3];
__device__ __align__(16) float g_O0 [LSEQ * 512];
__device__ __align__(16) float g_H1 [LSEQ * 512];
__device__ __align__(16) float g_EO [LSEQ * 512];
__device__ int   g_G0flag[NCHUNK];   // counts to NWORK0 (Gi0 tiles ready)
__device__ int   g_L0flag[NCHUNK];   // counts to 32 (L0 CTAs done with chunk)
__device__ int   g_Gflag [NCHUNK];   // counts to NWORK1 (Gi1 tiles ready)
__device__ int   g_H1flag[NCHUNK];   // counts to 32 (L1 CTAs done with chunk)
// decoder staging
__device__ __align__(16) float g_awl [NTAGS * 1024];
__device__ float g_Mx[NTAGS], g_Sx[NTAGS];
__device__ __align__(16) float g_ctxp[16 * NTAGS * 512];
__device__ __align__(16) float g_cat2[NTAGS * 1024];
__device__ __align__(16) float g_oo  [NTAGS * 512];
__device__ __align__(16) float g_gi  [NTAGS * 1536];
__device__ __align__(16) float g_gh  [1536];

// ---------------- helpers ----------------
__device__ __forceinline__ float wred_sum(float v) {
#pragma unroll
    for (int o = 16; o; o >>= 1) v += __shfl_xor_sync(0xffffffffu, v, o);
    return v;
}
__device__ __forceinline__ float wred_max(float v) {
#pragma unroll
    for (int o = 16; o; o >>= 1) v = fmaxf(v, __shfl_xor_sync(0xffffffffu, v, o));
    return v;
}
__device__ __forceinline__ float sigm(float x) { return 1.0f / (1.0f + expf(-x)); }
__device__ __forceinline__ float fsigm(float x) { return __fdividef(1.0f, 1.0f + __expf(-x)); }
__device__ __forceinline__ float ftanh(float x) {
    return 1.0f - __fdividef(2.0f, __expf(2.0f * x) + 1.0f);
}
__device__ __forceinline__ void cluster_sync_asm() {
    asm volatile("barrier.cluster.arrive.aligned;" ::: "memory");
    asm volatile("barrier.cluster.wait.aligned;" ::: "memory");
}
__device__ __forceinline__ uint32_t mapa_sc(uint32_t la, uint32_t r) {
    uint32_t ra;
    asm("mapa.shared::cluster.u32 %0, %1, %2;" : "=r"(ra) : "r"(la), "r"(r));
    return ra;
}
__device__ __forceinline__ void st_async_b32(uint32_t raddr, uint32_t v, uint32_t rmbar) {
    asm volatile("st.async.weak.shared::cluster.mbarrier::complete_tx::bytes.b32 [%0], %1, [%2];"
                 :: "r"(raddr), "r"(v), "r"(rmbar) : "memory");
}
__device__ __forceinline__ void mbar_init(uint32_t mb, uint32_t cnt) {
    asm volatile("mbarrier.init.shared.b64 [%0], %1;" :: "r"(mb), "r"(cnt) : "memory");
}
__device__ __forceinline__ void mbar_arrive_expect(uint32_t mb, uint32_t bytes) {
    asm volatile("mbarrier.arrive.expect_tx.shared.b64 _, [%0], %1;" :: "r"(mb), "r"(bytes) : "memory");
}
__device__ __forceinline__ void mbar_wait_parity(uint32_t mb, uint32_t parity) {
    uint32_t done;
    asm volatile(
        "{\n\t.reg .pred p;\n\t"
        "mbarrier.try_wait.parity.acquire.cluster.shared::cta.b64 p, [%1], %2;\n\t"
        "selp.b32 %0, 1, 0, p;\n\t}"
        : "=r"(done) : "r"(mb), "r"(parity) : "memory");
    if (!done) {
        asm volatile(
            "{\n\t.reg .pred P1;\n\t"
            "WL_%=:\n\t"
            "mbarrier.try_wait.parity.acquire.cluster.shared::cta.b64 P1, [%0], %1, 0x989680;\n\t"
            "@P1 bra.uni WD_%=;\n\t"
            "bra.uni WL_%=;\n\t"
            "WD_%=:\n\t}"
            :: "r"(mb), "r"(parity) : "memory");
    }
}
__device__ __forceinline__ int ld_acq_gpu(const int* p) {
    int v;
    asm volatile("ld.acquire.gpu.global.b32 %0, [%1];" : "=r"(v) : "l"(p) : "memory");
    return v;
}
__device__ __forceinline__ void membar_gpu() {
    asm volatile("membar.gl;" ::: "memory");
}

// ---------------- flag init ----------------
__global__ void init_flags_kernel()
{
    int i = threadIdx.x;
    if (i < NCHUNK) {
        g_G0flag[i] = 0;
        g_L0flag[i] = 0;
        g_Gflag[i]  = 0;
        g_H1flag[i] = 0;
    }
}

// ---------------- fused pipelined encoder (R9 protocol, CHUNK=32) ----------------
// bid 0-63:    4 clusters of 16 = cells L0f, L0b, L1f, L1b (recurrence)
// bid 64-87:   24 Gi1 workers (BM=32 tile, wait L0flag)
// bid 88-111:  24 Gi0 workers (BM=32 tile, no wait)
// bid 112-115: 4 EO workers (log_softmax rows, wait H1flag)
// bid 116-127: pad, exit
__global__ void __cluster_dims__(CLN, 1, 1) fused_kernel(
    const float* __restrict__ Whh0f, const float* __restrict__ bhh0f,
    const float* __restrict__ Whh0b, const float* __restrict__ bhh0b,
    const float* __restrict__ Whh1f, const float* __restrict__ bhh1f,
    const float* __restrict__ Whh1b, const float* __restrict__ bhh1b,
    const float* __restrict__ Wih1f, const float* __restrict__ bih1f,
    const float* __restrict__ Wih1b, const float* __restrict__ bih1b,
    const float* __restrict__ Wih0f, const float* __restrict__ bih0f,
    const float* __restrict__ Wih0b, const float* __restrict__ bih0b,
    const int*   __restrict__ x,     const float* __restrict__ emb,
    const float* __restrict__ hinit)
{
    __shared__ __align__(16) float hbuf[2][256];
    __shared__ __align__(16) float red3[48];
    __shared__ __align__(16) float gis[48];
    __shared__ __align__(16) float bhhs[48];
    __shared__ __align__(16) float As[32][68];
    __shared__ __align__(16) float Bs[32][68];
    __shared__ __align__(8)  uint64_t s_mb;

    int bid = blockIdx.x;
    int tid = threadIdx.x;

    if (bid < NRECUR) {
        // ================= recurrence cell =================
        int cell = bid >> 4;          // 0=L0f 1=L0b 2=L1f 3=L1b
        int isL1 = cell >> 1;
        int col  = cell & 1;
        unsigned rank;
        asm("mov.u32 %0, %%cluster_ctarank;" : "=r"(rank));

        const float* Gi  = isL1 ? (col ? g_Gi1B : g_Gi1F) : (col ? g_GiB : g_GiF);
        const float* Whh = (cell == 0) ? Whh0f : (cell == 1) ? Whh0b : (cell == 2) ? Whh1f : Whh1b;
        const float* bhh = (cell == 0) ? bhh0f : (cell == 1) ? bhh0b : (cell == 2) ? bhh1f : bhh1b;
        float* Out       = isL1 ? g_H1 : g_O0;
        const int* inFlag = isL1 ? g_Gflag : g_G0flag;
        int inTarget      = isL1 ? NWORK1 : NWORK0;
        int* outFlag      = isL1 ? g_H1flag : g_L0flag;

        int q  = tid & 7;             // K-chunk of 32
        int rl = tid >> 3;            // 0..47  (gate-row local)
        int g  = rl >> 4, jj = rl & 15;
        int rowGlobal = g * 256 + (int)rank * 16 + jj;
        int w    = tid >> 5;
        int lane = tid & 31;

        // weights loaded in q-rotated order so the h-read is bank-conflict-free
        float4 w4[8];
        const float* wp = Whh + (size_t)rowGlobal * 256 + q * 32;
#pragma unroll
        for (int i = 0; i < 8; i++) {
            int ii = (i + q) & 7;
            w4[i] = *(const float4*)(wp + ii * 4);
        }

        uint32_t mb = (uint32_t)__cvta_generic_to_shared(&s_mb);
        if (tid == 0) mbar_init(mb, 1);
        if (tid < 256) hbuf[0][tid] = hinit[cell * 256 + tid];
        if (tid < 48)  bhhs[tid] = bhh[(tid >> 4) * 256 + (int)rank * 16 + (tid & 15)];
        __syncthreads();
        cluster_sync_asm();

        // remote addresses. warp w -> dest w; warps 8-11 also -> dest w+4.
        uint32_t ra0a = 0, ra1a = 0, rma = 0, ra0b = 0, ra1b = 0, rmb2 = 0;
        {
            uint32_t la0 = (uint32_t)__cvta_generic_to_shared(&hbuf[0][rank * 16 + lane]);
            uint32_t la1 = (uint32_t)__cvta_generic_to_shared(&hbuf[1][rank * 16 + lane]);
            ra0a = mapa_sc(la0, (uint32_t)w);
            ra1a = mapa_sc(la1, (uint32_t)w);
            rma  = mapa_sc(mb,  (uint32_t)w);
            if (w >= 8) {
                ra0b = mapa_sc(la0, (uint32_t)(w + 4));
                ra1b = mapa_sc(la1, (uint32_t)(w + 4));
                rmb2 = mapa_sc(mb,  (uint32_t)(w + 4));
            }
        }

        float gi_cur = 0.f;

        for (int t = 0; t < LSEQ; t++) {
            int cur = t & 1;
            bool last = (t == LSEQ - 1);

            if ((t & (CHUNK - 1)) == 0) {
                if (tid == 0) {
                    int k = t >> CSHIFT;
                    while (ld_acq_gpu(&inFlag[k]) < inTarget) __nanosleep(128);
                }
                __syncthreads();
                if (tid < 48) gi_cur = Gi[(size_t)t * G3 + (tid >> 4) * 256 + (int)rank * 16 + (tid & 15)];
            }

            if (!last && tid == 0) mbar_arrive_expect(mb, 1024);
            if (tid < 48) {
                gis[tid] = gi_cur;
                bool pf = (t + 1 < LSEQ) && (((t + 1) & (CHUNK - 1)) != 0);
                if (pf) gi_cur = Gi[(size_t)(t + 1) * G3 + (tid >> 4) * 256 + (int)rank * 16 + (tid & 15)];
            }

            const float* hc = hbuf[cur] + q * 32;
            float ax = 0.f, ay = 0.f, az = 0.f, aw = 0.f;
#pragma unroll
            for (int i = 0; i < 8; i++) {
                int ii = (i + q) & 7;
                float4 hv = *(const float4*)(hc + ii * 4);
                ax += w4[i].x * hv.x; ay += w4[i].y * hv.y;
                az += w4[i].z * hv.z; aw += w4[i].w * hv.w;
            }
            float v = (ax + ay) + (az + aw);
            v += __shfl_xor_sync(0xffffffffu, v, 1);
            v += __shfl_xor_sync(0xffffffffu, v, 2);
            v += __shfl_xor_sync(0xffffffffu, v, 4);
            if (q == 0) red3[rl] = v;
            __syncthreads();

            if (lane < 16) {
                float ghr = red3[lane]      + bhhs[lane];
                float ghz = red3[16 + lane] + bhhs[16 + lane];
                float ghn = red3[32 + lane] + bhhs[32 + lane];
                float r = fsigm(gis[lane] + ghr);
                float z = fsigm(gis[16 + lane] + ghz);
                float n = ftanh(gis[32 + lane] + r * ghn);
                float hp = hbuf[cur][rank * 16 + lane];
                float hn_ = (1.0f - z) * n + z * hp;
                uint32_t hv = __float_as_uint(hn_);

                if (!last) {
                    st_async_b32(cur ? ra0a : ra1a, hv, rma);
                    if (w >= 8) st_async_b32(cur ? ra0b : ra1b, hv, rmb2);
                }

                if (w == 0)
                    Out[(size_t)t * 512 + col * 256 + rank * 16 + lane] = hn_;
            }
            if (w == 0 && (t & (CHUNK - 1)) == (CHUNK - 1)) {
                __syncwarp();
                if (lane == 0) {
                    membar_gpu();
                    atomicAdd(&outFlag[t >> CSHIFT], 1);
                }
            }
            if (!last) mbar_wait_parity(mb, (uint32_t)(t & 1));
        }
    } else if (bid < NRECUR + NWORK1) {
        // ================= Gi1 worker: Gi1 = Wih1 @ O0 (K=512), BM=32 chunked =================
        int ww = bid - NRECUR;            // 0..23
        int cellb = ww / 12;              // 0=f 1=b
        int nt = ww % 12;
        const float* W   = cellb ? Wih1b : Wih1f;
        const float* bih = cellb ? bih1b : bih1f;
        float* Gi        = cellb ? g_Gi1B : g_Gi1F;

        bool act = tid < 256;
        int at = act ? tid : 0;
        int ty = at >> 4, tx = at & 15;       // ty: 2 rows each; tx: 4 cols each
        int lrB = at >> 2;                    // 0..63 (B rows)
        int kcB = (at & 3) * 8;
        int lrA = at >> 3;                    // 0..31 (A rows)
        int kcA = (at & 7) * 4;

        for (int k = 0; k < NCHUNK; k++) {
            if (tid == 0) {
                while (ld_acq_gpu(&g_L0flag[k]) < 32) __nanosleep(128);
            }
            __syncthreads();

            int m0 = k * CHUNK;
            int n0 = nt * 64;
            const float* arow = g_O0 + (size_t)(m0 + lrA) * 512;
            const float* brow = W + (size_t)(n0 + lrB) * 512;

            float acc[2][4] = {};
            for (int k0 = 0; k0 < 512; k0 += 32) {
                float4 a0, b0, b1;
                if (act) {
                    a0 = *(const float4*)(arow + k0 + kcA);
                    b0 = *(const float4*)(brow + k0 + kcB);
                    b1 = *(const float4*)(brow + k0 + kcB + 4);
                }
                __syncthreads();
                if (act) {
                    As[kcA+0][lrA]=a0.x; As[kcA+1][lrA]=a0.y; As[kcA+2][lrA]=a0.z; As[kcA+3][lrA]=a0.w;
                    Bs[kcB+0][lrB]=b0.x; Bs[kcB+1][lrB]=b0.y; Bs[kcB+2][lrB]=b0.z; Bs[kcB+3][lrB]=b0.w;
                    Bs[kcB+4][lrB]=b1.x; Bs[kcB+5][lrB]=b1.y; Bs[kcB+6][lrB]=b1.z; Bs[kcB+7][lrB]=b1.w;
                }
                __syncthreads();
                if (act) {
#pragma unroll
                    for (int kk = 0; kk < 32; kk++) {
                        float2 av = *(const float2*)&As[kk][ty * 2];
                        float4 bv = *(const float4*)&Bs[kk][tx * 4];
                        float a2[2] = {av.x, av.y};
                        float b4[4] = {bv.x, bv.y, bv.z, bv.w};
#pragma unroll
                        for (int i = 0; i < 2; i++)
#pragma unroll
                            for (int j = 0; j < 4; j++)
                                acc[i][j] += a2[i] * b4[j];
                    }
                }
            }
            if (act) {
#pragma unroll
                for (int i = 0; i < 2; i++) {
                    int m = m0 + ty * 2 + i;
#pragma unroll
                    for (int j = 0; j < 4; j++) {
                        int n = n0 + tx * 4 + j;
                        Gi[(size_t)m * G3 + n] = acc[i][j] + bih[n];
                    }
                }
            }
            __syncthreads();
            if (tid == 0) {
                membar_gpu();
                atomicAdd(&g_Gflag[k], 1);
            }
        }
    } else if (bid < NRECUR + NWORK1 + NWORK0) {
        // ================= Gi0 worker: Gi0 = Wih0 @ emb[x] (K=256), BM=32, no wait =================
        int ww = bid - NRECUR - NWORK1;   // 0..23
        int cellb = ww / 12;
        int nt = ww % 12;
        const float* W   = cellb ? Wih0b : Wih0f;
        const float* bih = cellb ? bih0b : bih0f;
        float* Gi        = cellb ? g_GiB : g_GiF;

        bool act = tid < 256;
        int at = act ? tid : 0;
        int ty = at >> 4, tx = at & 15;
        int lrB = at >> 2;
        int kcB = (at & 3) * 8;
        int lrA = at >> 3;
        int kcA = (at & 7) * 4;

        for (int k = 0; k < NCHUNK; k++) {
            int m0 = k * CHUNK;
            int n0 = nt * 64;
            const float* arow = emb + (size_t)x[m0 + lrA] * 256;
            const float* brow = W + (size_t)(n0 + lrB) * 256;

            float acc[2][4] = {};
            for (int k0 = 0; k0 < 256; k0 += 32) {
                float4 a0, b0, b1;
                if (act) {
                    a0 = *(const float4*)(arow + k0 + kcA);
                    b0 = *(const float4*)(brow + k0 + kcB);
                    b1 = *(const float4*)(brow + k0 + kcB + 4);
                }
                __syncthreads();
                if (act) {
                    As[kcA+0][lrA]=a0.x; As[kcA+1][lrA]=a0.y; As[kcA+2][lrA]=a0.z; As[kcA+3][lrA]=a0.w;
                    Bs[kcB+0][lrB]=b0.x; Bs[kcB+1][lrB]=b0.y; Bs[kcB+2][lrB]=b0.z; Bs[kcB+3][lrB]=b0.w;
                    Bs[kcB+4][lrB]=b1.x; Bs[kcB+5][lrB]=b1.y; Bs[kcB+6][lrB]=b1.z; Bs[kcB+7][lrB]=b1.w;
                }
                __syncthreads();
                if (act) {
#pragma unroll
                    for (int kk = 0; kk < 32; kk++) {
                        float2 av = *(const float2*)&As[kk][ty * 2];
                        float4 bv = *(const float4*)&Bs[kk][tx * 4];
                        float a2[2] = {av.x, av.y};
                        float b4[4] = {bv.x, bv.y, bv.z, bv.w};
#pragma unroll
                        for (int i = 0; i < 2; i++)
#pragma unroll
                            for (int j = 0; j < 4; j++)
                                acc[i][j] += a2[i] * b4[j];
                    }
                }
            }
            if (act) {
#pragma unroll
                for (int i = 0; i < 2; i++) {
                    int m = m0 + ty * 2 + i;
#pragma unroll
                    for (int j = 0; j < 4; j++) {
                        int n = n0 + tx * 4 + j;
                        Gi[(size_t)m * G3 + n] = acc[i][j] + bih[n];
                    }
                }
            }
            __syncthreads();
            if (tid == 0) {
                membar_gpu();
                atomicAdd(&g_G0flag[k], 1);
            }
        }
    } else if (bid < NRECUR + NWORK1 + NWORK0 + NEO) {
        // ================= EO worker: log_softmax(H1 rows), chunked =================
        int eo = bid - NRECUR - NWORK1 - NWORK0;  // 0..3
        int w = tid >> 5, lane = tid & 31;

        for (int k = 0; k < NCHUNK; k++) {
            if (tid == 0) {
                while (ld_acq_gpu(&g_H1flag[k]) < 32) __nanosleep(128);
            }
            __syncthreads();

            int base = k * CHUNK + eo * 8;   // 8 rows per EO CTA per chunk
            if (w < 8) {
                int row = base + w;
                const float4* hr = (const float4*)(g_H1 + (size_t)row * 512);
                float4 v[4];
#pragma unroll
                for (int i = 0; i < 4; i++) v[i] = hr[lane + i * 32];
                float m = -1e30f;
#pragma unroll
                for (int i = 0; i < 4; i++)
                    m = fmaxf(m, fmaxf(fmaxf(v[i].x, v[i].y), fmaxf(v[i].z, v[i].w)));
                m = wred_max(m);
                float s = 0.f;
#pragma unroll
                for (int i = 0; i < 4; i++)
                    s += expf(v[i].x - m) + expf(v[i].y - m) + expf(v[i].z - m) + expf(v[i].w - m);
                s = wred_sum(s);
                float lg = m + logf(s);
                float4* er = (float4*)(g_EO + (size_t)row * 512);
#pragma unroll
                for (int i = 0; i < 4; i++) {
                    float4 o4 = {v[i].x - lg, v[i].y - lg, v[i].z - lg, v[i].w - lg};
                    er[lane + i * 32] = o4;
                }
            }
            __syncthreads();
        }
    }
    // pad CTAs (bid >= 116) fall through and exit
}

// ================= decoder stage kernels (tag-batched, wide) =================

// grid 128 x 256: 8 rows/CTA, 1 row per warp
__global__ void dec_attn_kernel(const float* __restrict__ de_emb,
                                const float* __restrict__ attn_W,
                                const float* __restrict__ attn_b)
{
    __shared__ __align__(16) float s_cat[NTAGS][1024];
    int tid = threadIdx.x, lane = tid & 31, w = tid >> 5;

    for (int i = tid; i < NTAGS * 1024; i += 256) {
        int tag = i >> 10, j = i & 1023;
        float v;
        if (j < 512) v = de_emb[tag * 512 + j];
        else {
            int jj = j - 512;
            v = (jj < 256) ? g_O0[(size_t)(LSEQ - 1) * 512 + jj]
                           : g_H1[(size_t)(LSEQ - 1) * 512 + jj];
        }
        s_cat[tag][j] = v;
    }
    __syncthreads();

    int m = blockIdx.x * 8 + w;
    const float4* wr = (const float4*)(attn_W + (size_t)m * 1024);
    float acc[NTAGS] = {};
#pragma unroll
    for (int i = 0; i < 8; i++) {
        float4 wv = wr[lane + i * 32];
#pragma unroll
        for (int tg = 0; tg < NTAGS; tg++) {
            float4 cv = *(const float4*)&s_cat[tg][(lane + i * 32) * 4];
            acc[tg] += wv.x * cv.x + wv.y * cv.y + wv.z * cv.z + wv.w * cv.w;
        }
    }
#pragma unroll
    for (int tg = 0; tg < NTAGS; tg++) {
        float a = wred_sum(acc[tg]);
        if (lane == 0) g_awl[tg * 1024 + m] = a + attn_b[m];
    }
}

__global__ void dec_softmax_kernel()
{
    int tag = blockIdx.x, tid = threadIdx.x, lane = tid & 31, w = tid >> 5;
    __shared__ float sr[8];
    float4 v = *(const float4*)(g_awl + tag * 1024 + tid * 4);
    float m = fmaxf(fmaxf(v.x, v.y), fmaxf(v.z, v.w));
    m = wred_max(m);
    if (lane == 0) sr[w] = m;
    __syncthreads();
    if (w == 0) {
        float mm = (lane < 8) ? sr[lane] : -1e30f;
        mm = wred_max(mm);
        if (lane == 0) sr[0] = mm;
    }
    __syncthreads();
    float M = sr[0];
    float s = expf(v.x - M) + expf(v.y - M) + expf(v.z - M) + expf(v.w - M);
    s = wred_sum(s);
    __syncthreads();
    if (lane == 0) sr[w] = s;
    __syncthreads();
    if (tid == 0) {
        float ss = 0.f;
        for (int i = 0; i < 8; i++) ss += sr[i];
        g_Mx[tag] = M;
        g_Sx[tag] = ss;
    }
}

__global__ void dec_ctx_kernel()
{
    __shared__ float p6[NTAGS][64];
    int ts = blockIdx.x, tid = threadIdx.x;
    int t0 = ts * 64;
    for (int i = tid; i < NTAGS * 64; i += 256) {
        int tag = i >> 6, tt = i & 63;
        p6[tag][tt] = expf(g_awl[tag * 1024 + t0 + tt] - g_Mx[tag]) / g_Sx[tag];
    }
    __syncthreads();

    int j0 = tid * 2;
    float acc[NTAGS][2] = {};
    for (int tt = 0; tt < 64; tt++) {
        float2 e = *(const float2*)(g_EO + (size_t)(t0 + tt) * 512 + j0);
#pragma unroll
        for (int tg = 0; tg < NTAGS; tg++) {
            float p = p6[tg][tt];
            acc[tg][0] += p * e.x;
            acc[tg][1] += p * e.y;
        }
    }
#pragma unroll
    for (int tg = 0; tg < NTAGS; tg++) {
        g_ctxp[(ts * NTAGS + tg) * 512 + j0]     = acc[tg][0];
        g_ctxp[(ts * NTAGS + tg) * 512 + j0 + 1] = acc[tg][1];
    }
}

__global__ void dec_cat2_kernel(const float* __restrict__ de_emb)
{
    int tag = blockIdx.x, tid = threadIdx.x;
    for (int j = tid; j < 512; j += 256) g_cat2[tag * 1024 + j] = de_emb[tag * 512 + j];
    for (int j = tid; j < 512; j += 256) {
        float s = 0.f;
#pragma unroll
        for (int ts = 0; ts < 16; ts++) s += g_ctxp[(ts * NTAGS + tag) * 512 + j];
        g_cat2[tag * 1024 + 512 + j] = s;
    }
}

__global__ void dec_comb_kernel(const float* __restrict__ comb_W,
                                const float* __restrict__ comb_b)
{
    __shared__ __align__(16) float s_cat[NTAGS][1024];
    int tid = threadIdx.x, lane = tid & 31, w = tid >> 5;
    for (int i = tid; i < NTAGS * 1024; i += 256) s_cat[i >> 10][i & 1023] = g_cat2[i];
    __syncthreads();

    for (int r = 0; r < 2; r++) {
        int m = blockIdx.x * 16 + w * 2 + r;
        const float4* wr = (const float4*)(comb_W + (size_t)m * 1024);
        float acc[NTAGS] = {};
#pragma unroll
        for (int i = 0; i < 8; i++) {
            float4 wv = wr[lane + i * 32];
#pragma unroll
            for (int tg = 0; tg < NTAGS; tg++) {
                float4 cv = *(const float4*)&s_cat[tg][(lane + i * 32) * 4];
                acc[tg] += wv.x * cv.x + wv.y * cv.y + wv.z * cv.z + wv.w * cv.w;
            }
        }
#pragma unroll
        for (int tg = 0; tg < NTAGS; tg++) {
            float a = wred_sum(acc[tg]);
            if (lane == 0) g_oo[tg * 512 + m] = fmaxf(a + comb_b[m], 0.f);
        }
    }
}

__global__ void dec_gates_kernel(const float* __restrict__ de_Wih,
                                 const float* __restrict__ de_Whh,
                                 const float* __restrict__ de_bih,
                                 const float* __restrict__ de_bhh)
{
    __shared__ __align__(16) float s_o[NTAGS][512];
    __shared__ __align__(16) float s_dh[512];
    int tid = threadIdx.x, lane = tid & 31, w = tid >> 5;
    for (int i = tid; i < NTAGS * 512; i += 256) s_o[i >> 9][i & 511] = g_oo[i];
    for (int i = tid; i < 512; i += 256)
        s_dh[i] = (i < 256) ? g_O0[(size_t)(LSEQ - 1) * 512 + i]
                            : g_H1[(size_t)(LSEQ - 1) * 512 + i];
    __syncthreads();

    int wg = blockIdx.x * 8 + w;   // 0..767
    for (int r = 0; r < 4; r++) {
        int job = wg * 4 + r;      // 0..3071
        if (job < 1536) {
            const float4* wr = (const float4*)(de_Whh + (size_t)job * 512);
            float acc = 0.f;
#pragma unroll
            for (int i = 0; i < 4; i++) {
                float4 wv = wr[lane + i * 32];
                float4 cv = *(const float4*)&s_dh[(lane + i * 32) * 4];
                acc += wv.x * cv.x + wv.y * cv.y + wv.z * cv.z + wv.w * cv.w;
            }
            acc = wred_sum(acc);
            if (lane == 0) g_gh[job] = acc + de_bhh[job];
        } else {
            int m = job - 1536;
            const float4* wr = (const float4*)(de_Wih + (size_t)m * 512);
            float acc[NTAGS] = {};
#pragma unroll
            for (int i = 0; i < 4; i++) {
                float4 wv = wr[lane + i * 32];
#pragma unroll
                for (int tg = 0; tg < NTAGS; tg++) {
                    float4 cv = *(const float4*)&s_o[tg][(lane + i * 32) * 4];
                    acc[tg] += wv.x * cv.x + wv.y * cv.y + wv.z * cv.z + wv.w * cv.w;
                }
            }
#pragma unroll
            for (int tg = 0; tg < NTAGS; tg++) {
                float a = wred_sum(acc[tg]);
                if (lane == 0) g_gi[tg * 1536 + m] = a + de_bih[m];
            }
        }
    }
}

__global__ void dec_final_kernel(const float* __restrict__ h2t_W,
                                 const float* __restrict__ h2t_b,
                                 float* __restrict__ out)
{
    __shared__ __align__(16) float s_hn[NTAGS][512];
    __shared__ __align__(16) float s_dh[512];
    __shared__ float s_lg[NTAGS][NTAGS];
    __shared__ float s_rowsum[NTAGS], s_val[NTAGS], s_b[NTAGS];
    __shared__ int   s_seq[8];
    __shared__ int   s_tail, s_per;

    int tid = threadIdx.x, lane = tid & 31, w = tid >> 5;

    if (tid < 512)
        s_dh[tid] = (tid < 256) ? g_O0[(size_t)(LSEQ - 1) * 512 + tid]
                                : g_H1[(size_t)(LSEQ - 1) * 512 + tid];
    __syncthreads();

    for (int idx = tid; idx < NTAGS * 512; idx += 1024) {
        int tag = idx >> 9, j = idx & 511;
        float gir = g_gi[tag * 1536 + j],        ghr = g_gh[j];
        float giz = g_gi[tag * 1536 + 512 + j],  ghz = g_gh[512 + j];
        float gin = g_gi[tag * 1536 + 1024 + j], ghn = g_gh[1024 + j];
        float r = sigm(gir + ghr);
        float z = sigm(giz + ghz);
        float n = tanhf(gin + r * ghn);
        s_hn[tag][j] = (1.0f - z) * n + z * s_dh[j];
    }
    __syncthreads();

    for (int job = w; job < 42; job += 32) {
        if (job < 36) {
            int tag = job / NTAGS, k = job % NTAGS;
            const float4* wr = (const float4*)(h2t_W + (size_t)k * 512);
            float acc = 0.f;
#pragma unroll
            for (int i = 0; i < 4; i++) {
                float4 wv = wr[lane + i * 32];
                float4 cv = *(const float4*)&s_hn[tag][(lane + i * 32) * 4];
                acc += wv.x * cv.x + wv.y * cv.y + wv.z * cv.z + wv.w * cv.w;
            }
            acc = wred_sum(acc);
            if (lane == 0) s_lg[tag][k] = acc + h2t_b[k];
        } else {
            int k = job - 36;
            float acc = 0.f;
            for (int i = lane; i < 512; i += 32) acc += h2t_W[(size_t)k * 512 + i];
            acc = wred_sum(acc);
            if (lane == 0) { s_rowsum[k] = acc; s_b[k] = h2t_b[k]; }
        }
    }
    __syncthreads();

    if (tid == 0) {
        int nxt[NTAGS];
        for (int tg = 0; tg < NTAGS; tg++) {
            float mx = s_lg[tg][0]; int am = 0;
            for (int i = 1; i < NTAGS; i++)
                if (s_lg[tg][i] > mx) { mx = s_lg[tg][i]; am = i; }
            float se = 0.f;
            for (int i = 0; i < NTAGS; i++) se += expf(s_lg[tg][i] - mx);
            s_val[tg] = s_lg[tg][0] - mx - logf(se);
            nxt[tg] = am;
        }
        int s = START_TAG;
        int seq[8];
        for (int i = 0; i < 8; i++) { seq[i] = s; s_seq[i] = s; s = nxt[s]; }
        int tail = 0, per = 1;
        bool found = false;
        for (int k = 1; k < 8 && !found; k++)
            for (int j = 0; j < k; j++)
                if (seq[k] == seq[j]) { tail = j; per = k - j; found = true; break; }
        s_tail = tail; s_per = per;
    }
    __syncthreads();

    int i = tid;
    int st = (i < s_tail) ? s_seq[i] : s_seq[s_tail + (i - s_tail) % s_per];
    float c = s_val[st];
#pragma unroll
    for (int t = 0; t < NTAGS; t++)
        out[(size_t)i * NTAGS + t] = c * s_rowsum[t] + s_b[t];
}

// ---------------- host ----------------
extern "C" void kernel_launch(void* const* d_in, const int* in_sizes, int n_in,
                              void* d_out, int out_size)
{
    const int*   x       = (const int*)  d_in[0];
    const float* emb     = (const float*)d_in[1];
    const float* Wih0f   = (const float*)d_in[2];
    const float* Whh0f   = (const float*)d_in[3];
    const float* bih0f   = (const float*)d_in[4];
    const float* bhh0f   = (const float*)d_in[5];
    const float* Wih0b   = (const float*)d_in[6];
    const float* Whh0b   = (const float*)d_in[7];
    const float* bih0b   = (const float*)d_in[8];
    const float* bhh0b   = (const float*)d_in[9];
    const float* Wih1f   = (const float*)d_in[10];
    const float* Whh1f   = (const float*)d_in[11];
    const float* bih1f   = (const float*)d_in[12];
    const float* bhh1f   = (const float*)d_in[13];
    const float* Wih1b   = (const float*)d_in[14];
    const float* Whh1b   = (const float*)d_in[15];
    const float* bih1b   = (const float*)d_in[16];
    const float* bhh1b   = (const float*)d_in[17];
    const float* ehid0   = (const float*)d_in[18];
    const float* de_emb  = (const float*)d_in[19];
    const float* attn_W  = (const float*)d_in[20];
    const float* attn_b  = (const float*)d_in[21];
    const float* comb_W  = (const float*)d_in[22];
    const float* comb_b  = (const float*)d_in[23];
    const float* de_Wih  = (const float*)d_in[24];
    const float* de_Whh  = (const float*)d_in[25];
    const float* de_bih  = (const float*)d_in[26];
    const float* de_bhh  = (const float*)d_in[27];
    const float* h2t_W   = (const float*)d_in[28];
    const float* h2t_b   = (const float*)d_in[29];
    float* out = (float*)d_out;

    cudaFuncSetAttribute(fused_kernel, cudaFuncAttributeNonPortableClusterSizeAllowed, 1);

    init_flags_kernel<<<1, 64>>>();
    fused_kernel<<<GRID_TOTAL, 384>>>(Whh0f, bhh0f, Whh0b, bhh0b,
                                      Whh1f, bhh1f, Whh1b, bhh1b,
                                      Wih1f, bih1f, Wih1b, bih1b,
                                      Wih0f, bih0f, Wih0b, bih0b,
                                      x, emb, ehid0);
    dec_attn_kernel<<<128, 256>>>(de_emb, attn_W, attn_b);
    dec_softmax_kernel<<<NTAGS, 256>>>();
    dec_ctx_kernel<<<16, 256>>>();
    dec_cat2_kernel<<<NTAGS, 256>>>(de_emb);
    dec_comb_kernel<<<32, 256>>>(comb_W, comb_b);
    dec_gates_kernel<<<96, 256>>>(de_Wih, de_Whh, de_bih, de_bhh);
    dec_final_kernel<<<1, 1024>>>(h2t_W, h2t_b, out);

    (void)in_sizes; (void)n_in; (void)out_size;
}